// round 14
// baseline (speedup 1.0000x reference)
#include <cuda_runtime.h>
#include <cuda_bf16.h>
#include <math.h>
#include <stdint.h>

#define NB   4
#define NTOK 4096
#define NC   192
#define MAXM 3969
#define BIMG 3456                        // B image words: 96 rows x 36 pitch
#define CSTGW 16128                      // conv stage: Ah4608+Al4608+B0 3456+B1 3456
#define PSTGW 11520                      // proj stage: Ah2304+Al2304+B0+B1
#define FSTGW 9216                       // flash stage words

static const float ATT_SCALE = 0.07216878364870323f; // 192^-0.5

// ---------------- scratch -------------------------------------------------------
__device__ float g_q[NB * NTOK * NC];
__device__ float g_t[(size_t)NB * MAXM * NC];
__device__ float g_kv[NB * MAXM * 128];
__device__ __nv_bfloat16 g_xh[NB * NTOK * NC];
__device__ __nv_bfloat16 g_xl[NB * NTOK * NC];
__device__ __nv_bfloat16 g_th[(size_t)NB * MAXM * NC];
__device__ __nv_bfloat16 g_tl[(size_t)NB * MAXM * NC];
__device__ uint32_t g_xch[NB * NTOK * 96];
__device__ uint32_t g_xcl[NB * NTOK * 96];
__device__ uint32_t g_wpack[768 * BIMG];
__device__ uint32_t g_wq[12 * BIMG];
__device__ uint32_t g_wkv[12 * BIMG];
__device__ uint32_t g_wnn[12 * BIMG];
__device__ __nv_bfloat16 g_qh[NB * NTOK * 64];
__device__ __nv_bfloat16 g_ql[NB * NTOK * 64];
__device__ uint32_t g_kvimg[NB * 63 * FSTGW];

// ---------------- helpers ---------------------------------------------------------
__device__ __forceinline__ uint32_t smem_u32(const void* p) {
    uint32_t a;
    asm("{ .reg .u64 t; cvta.to.shared.u64 t, %1; cvt.u32.u64 %0, t; }" : "=r"(a) : "l"(p));
    return a;
}
#define MMA16816(acc, a, b0, b1)                                                    \
    asm volatile("mma.sync.aligned.m16n8k16.row.col.f32.bf16.bf16.f32 "             \
        "{%0,%1,%2,%3}, {%4,%5,%6,%7}, {%8,%9}, {%0,%1,%2,%3};"                     \
        : "+f"((acc)[0]), "+f"((acc)[1]), "+f"((acc)[2]), "+f"((acc)[3])            \
        : "r"((a)[0]), "r"((a)[1]), "r"((a)[2]), "r"((a)[3]), "r"(b0), "r"(b1))
#define LDSM4(r0, r1, r2, r3, addr)                                                 \
    asm volatile("ldmatrix.sync.aligned.m8n8.x4.shared.b16 {%0,%1,%2,%3}, [%4];"    \
        : "=r"(r0), "=r"(r1), "=r"(r2), "=r"(r3) : "r"(addr))
#define LDSM2(r0, r1, addr)                                                         \
    asm volatile("ldmatrix.sync.aligned.m8n8.x2.shared.b16 {%0,%1}, [%2];"          \
        : "=r"(r0), "=r"(r1) : "r"(addr))
#define CPA16(dst, src)                                                             \
    asm volatile("cp.async.cg.shared.global [%0], [%1], 16;"                        \
        :: "r"(dst), "l"(src))
#define CPA_COMMIT() asm volatile("cp.async.commit_group;" ::: "memory")
#define CPA_WAIT1()  asm volatile("cp.async.wait_group 1;" ::: "memory")

__device__ __forceinline__ void split2(float a, float b, uint32_t& hi, uint32_t& lo) {
    __nv_bfloat16 ha = __float2bfloat16(a), hb = __float2bfloat16(b);
    float ra = a - __bfloat162float(ha);
    float rb = b - __bfloat162float(hb);
    __nv_bfloat16 la = __float2bfloat16(ra), lb = __float2bfloat16(rb);
    hi = ((uint32_t)*(unsigned short*)&hb << 16) | *(unsigned short*)&ha;
    lo = ((uint32_t)*(unsigned short*)&lb << 16) | *(unsigned short*)&la;
}

// ---------------- prep: split x into bf16 hi/lo -----------------------------------
__global__ void prep_x_kernel(const float* __restrict__ x, __nv_bfloat16* __restrict__ xh,
                              __nv_bfloat16* __restrict__ xl) {
    int i = blockIdx.x * 256 + threadIdx.x;
    if (i >= NB * NTOK * NC) return;
    float f = x[i];
    __nv_bfloat16 h = __float2bfloat16(f);
    xh[i] = h;
    xl[i] = __float2bfloat16(f - __bfloat162float(h));
}

// ---------------- prep: W -> n-major packed word images -----------------------------
__global__ void prep_w_kernel(const float* __restrict__ w, uint32_t* __restrict__ wp,
                              int k2) {
    int idx = blockIdx.x * 256 + threadIdx.x;
    int total = k2 * 12 * BIMG;
    if (idx >= total) return;
    int img = idx / BIMG, rem = idx % BIMG;
    int n = rem / 36, c2 = rem % 36;
    if (c2 >= 32) { wp[idx] = 0u; return; }
    int tap = img / 12, r = img % 12;
    int cb = r >> 2, r2 = r & 3;
    int cohalf = r2 >> 1, split = r2 & 1;
    int ci = cb * 64 + 2 * c2;
    int co = cohalf * 96 + n;
    float fe = w[((size_t)co * NC + ci) * k2 + tap];
    float fo = w[((size_t)co * NC + ci + 1) * k2 + tap];
    __nv_bfloat16 he = __float2bfloat16(fe), ho = __float2bfloat16(fo);
    __nv_bfloat16 ve = split ? __float2bfloat16(fe - __bfloat162float(he)) : he;
    __nv_bfloat16 vo = split ? __float2bfloat16(fo - __bfloat162float(ho)) : ho;
    uint32_t we = *(const unsigned short*)&ve;
    uint32_t wo = *(const unsigned short*)&vo;
    wp[idx] = (wo << 16) | we;
}

// ---------------- shared compute core (ldmatrix + MMA) ------------------------------
// alo_b = A-lo byte offset from stage base; B base at bbase_b; B-lo at +13824 bytes.
#define HMMA_GROUP_COMPUTE(soff, alo_b)                                              \
    _Pragma("unroll")                                                                \
    for (int ks = 0; ks < 4; ks++) {                                                 \
        uint32_t kb = (uint32_t)(ks * 32);                                           \
        uint32_t ah[4], ah2[4], al[4], al2[4];                                       \
        LDSM4(ah[0], ah[1], ah[2], ah[3], aoff0 + (soff) + kb);                      \
        LDSM4(ah2[0], ah2[1], ah2[2], ah2[3], aoff1 + (soff) + kb);                  \
        LDSM4(al[0], al[1], al[2], al[3], aoff0 + (soff) + (alo_b) + kb);            \
        LDSM4(al2[0], al2[1], al2[2], al2[3], aoff1 + (soff) + (alo_b) + kb);        \
        uint32_t wh[3][2], wl[3][2];                                                 \
        LDSM4(wh[0][0], wh[0][1], wh[1][0], wh[1][1], boff01 + (soff) + kb);         \
        LDSM2(wh[2][0], wh[2][1], boff2 + (soff) + kb);                              \
        LDSM4(wl[0][0], wl[0][1], wl[1][0], wl[1][1], boff01 + (soff) + 13824u + kb);\
        LDSM2(wl[2][0], wl[2][1], boff2 + (soff) + 13824u + kb);                     \
        _Pragma("unroll")                                                            \
        for (int j = 0; j < 3; j++) {                                                \
            MMA16816(acc[0][j], ah, wh[j][0], wh[j][1]);                             \
            MMA16816(acc[0][j], ah, wl[j][0], wl[j][1]);                             \
            MMA16816(acc[0][j], al, wh[j][0], wh[j][1]);                             \
            MMA16816(acc[1][j], ah2, wh[j][0], wh[j][1]);                            \
            MMA16816(acc[1][j], ah2, wl[j][0], wl[j][1]);                            \
            MMA16816(acc[1][j], al2, wh[j][0], wh[j][1]);                            \
        }                                                                            \
    }

// ---------------- conv: 512 threads, 128px x 96co tile, cp.async x2 -----------------
__global__ void __launch_bounds__(512, 1) conv_hmma_kernel(
    const __nv_bfloat16* __restrict__ xh, const __nv_bfloat16* __restrict__ xl,
    const uint4* __restrict__ wp, const float* __restrict__ bias,
    float* __restrict__ out, int k, int side, int m)
{
    extern __shared__ uint32_t dsm[];

    int tid = threadIdx.x;
    int lane = tid & 31, wid = tid >> 5;
    int wm = wid & 3, wn = wid >> 2;
    long long Bm = (long long)NB * m;

    int arow = tid >> 2, aq = tid & 3;      // 128 rows x 4 threads
    long long apx = (long long)blockIdx.x * 128 + arow;
    long long apxc = apx < Bm - 1 ? apx : Bm - 1;
    int ab = (int)(apxc / m), app = (int)(apxc % m);
    int aoy = app / side, aox = app % side;
    size_t axbase = (size_t)ab * NTOK * NC;
    int half = blockIdx.y;
    int rA = lane >> 2, cA = lane & 3;

    uint32_t smbase = smem_u32(dsm);
    uint32_t awd = smbase + (uint32_t)(arow * 36 + aq * 8) * 4;
    uint32_t bwd = smbase + 9216u * 4;

    int lrow = lane & 15, lcol = lane >> 4;
    uint32_t aoff0 = smbase + (uint32_t)((wm * 32 + lrow) * 144 + lcol * 16);
    uint32_t aoff1 = aoff0 + 16 * 144;
    int brow = (lane & 7) + ((lane & 16) ? 8 : 0);
    int bcolb = ((lane >> 3) & 1) * 16;
    uint32_t boff01 = smbase + 9216u * 4 + (uint32_t)((wn * 24 + brow) * 144 + bcolb);
    uint32_t boff2  = smbase + 9216u * 4 + (uint32_t)((wn * 24 + 16 + (lane & 7)) * 144
                                                      + bcolb);

    float acc[2][3][4];
#pragma unroll
    for (int i = 0; i < 2; i++)
#pragma unroll
        for (int j = 0; j < 3; j++)
#pragma unroll
            for (int q = 0; q < 4; q++) acc[i][j][q] = 0.f;

    int k2 = k * k;
    int ng = k2 * 3;

#define CONV_ISSUE(g, s) do {                                                        \
        int _tap = (g) / 3, _cb = (g) - _tap * 3;                                    \
        int _dy = _tap / k, _dx = _tap - _dy * k;                                    \
        size_t _aoff = axbase + (size_t)((aoy + _dy) * 64 + aox + _dx) * NC          \
                     + _cb * 64 + aq * 16;                                           \
        uint32_t _soff = (uint32_t)(s) * (CSTGW * 4);                                \
        const char* _gh = (const char*)(xh + _aoff);                                 \
        const char* _gl = (const char*)(xl + _aoff);                                 \
        CPA16(awd + _soff,      _gh);                                                \
        CPA16(awd + _soff + 16, _gh + 16);                                           \
        CPA16(awd + _soff + 4608u * 4,      _gl);                                    \
        CPA16(awd + _soff + 4608u * 4 + 16, _gl + 16);                               \
        int _imgb = (_tap * 3 + _cb) * 4 + half * 2;                                 \
        const char* _gb = (const char*)(wp + (size_t)_imgb * (BIMG / 4));            \
        _Pragma("unroll")                                                            \
        for (int _i = 0; _i < 4; _i++) {                                             \
            int _idx = tid + _i * 512;                                               \
            if (_idx < 1728) CPA16(bwd + _soff + _idx * 16, _gb + (size_t)_idx * 16);\
        }                                                                            \
    } while (0)

    CONV_ISSUE(0, 0);
    CPA_COMMIT();

    for (int g = 0; g < ng; g++) {
        if (g + 1 < ng) CONV_ISSUE(g + 1, (g + 1) & 1);
        CPA_COMMIT();
        CPA_WAIT1();
        __syncthreads();

        uint32_t soff = (uint32_t)(g & 1) * (CSTGW * 4);
        HMMA_GROUP_COMPUTE(soff, 18432u);
        __syncthreads();
    }
#undef CONV_ISSUE

#pragma unroll
    for (int i = 0; i < 2; i++) {
        long long row0 = (long long)blockIdx.x * 128 + wm * 32 + i * 16 + rA;
#pragma unroll
        for (int j = 0; j < 3; j++) {
            int col = half * 96 + wn * 24 + j * 8 + 2 * cA;
            float b0 = bias[col], b1 = bias[col + 1];
            if (row0 < Bm) {
                float2 v = make_float2(acc[i][j][0] + b0, acc[i][j][1] + b1);
                *(float2*)&out[row0 * NC + col] = v;
            }
            if (row0 + 8 < Bm) {
                float2 v = make_float2(acc[i][j][2] + b0, acc[i][j][3] + b1);
                *(float2*)&out[(row0 + 8) * NC + col] = v;
            }
        }
    }
}

// ---------------- projection GEMM on HMMA + ldmatrix (256 thr, unchanged) -----------
__global__ void __launch_bounds__(256, 2) gemm_hmma_kernel(
    const __nv_bfloat16* __restrict__ Ah_g, const __nv_bfloat16* __restrict__ Al_g,
    const uint4* __restrict__ wimg, const float* __restrict__ bias,
    float* __restrict__ out, long long rows, int ldout, int Nout)
{
    extern __shared__ uint32_t dsm[];

    int tid = threadIdx.x;
    int lane = tid & 31, wid = tid >> 5;
    int wm = wid & 1, wn = wid >> 1;

    int arow = tid >> 2, aq = tid & 3;
    long long r = (long long)blockIdx.x * 64 + arow;
    long long rc = r < rows - 1 ? r : rows - 1;
    int half = blockIdx.y;
    int rA = lane >> 2, cA = lane & 3;

    uint32_t smbase = smem_u32(dsm);
    uint32_t awd = smbase + (uint32_t)(arow * 36 + aq * 8) * 4;
    uint32_t bwd = smbase + 4608u * 4;

    int lrow = lane & 15, lcol = lane >> 4;
    uint32_t aoff0 = smbase + (uint32_t)((wm * 32 + lrow) * 144 + lcol * 16);
    uint32_t aoff1 = aoff0 + 16 * 144;
    int brow = (lane & 7) + ((lane & 16) ? 8 : 0);
    int bcolb = ((lane >> 3) & 1) * 16;
    uint32_t boff01 = smbase + 4608u * 4 + (uint32_t)((wn * 24 + brow) * 144 + bcolb);
    uint32_t boff2  = smbase + 4608u * 4 + (uint32_t)((wn * 24 + 16 + (lane & 7)) * 144
                                                      + bcolb);

    float acc[2][3][4];
#pragma unroll
    for (int i = 0; i < 2; i++)
#pragma unroll
        for (int j = 0; j < 3; j++)
#pragma unroll
            for (int q = 0; q < 4; q++) acc[i][j][q] = 0.f;

#define PROJ_ISSUE(g, s) do {                                                        \
        size_t _aoff = (size_t)rc * NC + (g) * 64 + aq * 16;                         \
        uint32_t _soff = (uint32_t)(s) * (PSTGW * 4);                                \
        const char* _gh = (const char*)(Ah_g + _aoff);                               \
        const char* _gl = (const char*)(Al_g + _aoff);                               \
        CPA16(awd + _soff,      _gh);                                                \
        CPA16(awd + _soff + 16, _gh + 16);                                           \
        CPA16(awd + _soff + 2304u * 4,      _gl);                                    \
        CPA16(awd + _soff + 2304u * 4 + 16, _gl + 16);                               \
        int _imgb = (g) * 4 + half * 2;                                              \
        const char* _gb = (const char*)(wimg + (size_t)_imgb * (BIMG / 4));          \
        _Pragma("unroll")                                                            \
        for (int _i = 0; _i < 7; _i++) {                                             \
            int _idx = tid + _i * 256;                                               \
            if (_idx < 1728) CPA16(bwd + _soff + _idx * 16, _gb + (size_t)_idx * 16);\
        }                                                                            \
    } while (0)

    PROJ_ISSUE(0, 0);
    CPA_COMMIT();

    for (int g = 0; g < 3; g++) {
        if (g + 1 < 3) PROJ_ISSUE(g + 1, (g + 1) & 1);
        CPA_COMMIT();
        CPA_WAIT1();
        __syncthreads();

        uint32_t soff = (uint32_t)(g & 1) * (PSTGW * 4);
        HMMA_GROUP_COMPUTE(soff, 9216u);
        __syncthreads();
    }
#undef PROJ_ISSUE

#pragma unroll
    for (int i = 0; i < 2; i++) {
        long long row0 = (long long)blockIdx.x * 64 + wm * 32 + i * 16 + rA;
#pragma unroll
        for (int j = 0; j < 3; j++) {
            int col = half * 96 + wn * 24 + j * 8 + 2 * cA;
            if (col >= Nout) continue;
            float b0 = bias[col], b1 = bias[col + 1];
            if (row0 < rows) {
                float2 v = make_float2(acc[i][j][0] + b0, acc[i][j][1] + b1);
                *(float2*)&out[row0 * ldout + col] = v;
            }
            if (row0 + 8 < rows) {
                float2 v = make_float2(acc[i][j][2] + b0, acc[i][j][3] + b1);
                *(float2*)&out[(row0 + 8) * ldout + col] = v;
            }
        }
    }
}

// ---------------- prep q split ------------------------------------------------------
__global__ void prep_q_kernel(const float* __restrict__ q, __nv_bfloat16* __restrict__ qh,
                              __nv_bfloat16* __restrict__ ql, int h) {
    int i = blockIdx.x * 256 + threadIdx.x;
    if (i >= NB * NTOK * 64) return;
    int c = i & 63;
    int row = i >> 6;
    float f = q[(size_t)row * NC + h * 64 + c];
    __nv_bfloat16 hi = __float2bfloat16(f);
    qh[i] = hi;
    ql[i] = __float2bfloat16(f - __bfloat162float(hi));
}

// ---------------- fused dwconv + pack: kv -> per-chunk [kh|kl|vh|vl] images ----------
__global__ void pack_kv_kernel(const float* __restrict__ kv,
                               const float* __restrict__ lw, const float* __restrict__ lb,
                               uint32_t* __restrict__ img, int m, int nchunk, int side) {
    int idx = blockIdx.x * 256 + threadIdx.x;
    int total = NB * nchunk * FSTGW;
    if (idx >= total) return;
    int b = idx / (nchunk * FSTGW);
    int rem = idx % (nchunk * FSTGW);
    int c = rem / FSTGW;
    int r2 = rem % FSTGW;
    int sect = r2 / 2304;
    int r3 = r2 % 2304;
    int c2 = r3 / 72, n = r3 % 72;
    if (n >= 64) { img[idx] = 0u; return; }
    float f0, f1;
    if (sect < 2) {
        int mi = c * 64 + n;
        if (mi < m) {
            const float* kr = kv + ((size_t)b * m + mi) * 128;
            f0 = kr[2 * c2];
            f1 = kr[2 * c2 + 1];
        } else { f0 = f1 = 0.f; }
    } else {
        const float* vb = kv + (size_t)b * m * 128 + 64 + n;
#pragma unroll
        for (int e = 0; e < 2; e++) {
            int p = c * 64 + 2 * c2 + e;
            float r = 0.f;
            if (p < m) {
                int y = p / side, xx0 = p % side;
                float s = lb[n];
#pragma unroll
                for (int dy = 0; dy < 3; dy++) {
                    int yy = y + dy - 1;
                    if (yy < 0 || yy >= side) continue;
#pragma unroll
                    for (int dx = 0; dx < 3; dx++) {
                        int xx = xx0 + dx - 1;
                        if (xx < 0 || xx >= side) continue;
                        s += lw[n * 9 + dy * 3 + dx] * vb[(size_t)(yy * side + xx) * 128];
                    }
                }
                r = vb[(size_t)p * 128] + s;
            }
            if (e == 0) f0 = r; else f1 = r;
        }
    }
    uint32_t hi, lo;
    split2(f0, f1, hi, lo);
    img[idx] = (sect & 1) ? lo : hi;
}

// ---------------- fused flash attention (unchanged) ----------------------------------
__global__ void __launch_bounds__(256) attn_flash_kernel(
    const __nv_bfloat16* __restrict__ qh, const __nv_bfloat16* __restrict__ ql,
    const uint32_t* __restrict__ kvimg,
    uint32_t* __restrict__ xch, uint32_t* __restrict__ xcl,
    int hoff, int m, int nchunk)
{
    extern __shared__ uint32_t fsm[];
    uint32_t* sQh = fsm;
    uint32_t* sQl = fsm + 4608;

    int tid = threadIdx.x, lane = tid & 31, w = tid >> 5;
    int rA = lane >> 2, cA = lane & 3;
    int b = blockIdx.y;
    int q0 = blockIdx.x * 128;

    uint32_t stg_b = smem_u32(fsm) + 9216u * 4;

    {
        int arow = tid >> 1, ahalf = tid & 1;
        size_t off = ((size_t)b * NTOK + q0 + arow) * 64 + ahalf * 32;
        const uint4* sh = (const uint4*)(qh + off);
        const uint4* sl = (const uint4*)(ql + off);
        uint32_t* dh = sQh + arow * 36 + ahalf * 16;
        uint32_t* dl = sQl + arow * 36 + ahalf * 16;
#pragma unroll
        for (int j = 0; j < 4; j++) { *(uint4*)&dh[j * 4] = sh[j]; *(uint4*)&dl[j * 4] = sl[j]; }
    }

#define FL_ISSUE(c, s) do {                                                          \
        const char* _src = (const char*)(kvimg + ((size_t)b * nchunk + (c)) * FSTGW);\
        uint32_t _dst = stg_b + (uint32_t)(s) * (FSTGW * 4);                         \
        _Pragma("unroll")                                                            \
        for (int _t = 0; _t < 9; _t++) {                                             \
            int _idx = tid + _t * 256;                                               \
            CPA16(_dst + _idx * 16, _src + (size_t)_idx * 16);                       \
        }                                                                            \
    } while (0)

    float acc_o[8][4];
#pragma unroll
    for (int nn = 0; nn < 8; nn++)
#pragma unroll
        for (int q = 0; q < 4; q++) acc_o[nn][q] = 0.f;
    float mrun0 = -1e30f, mrun1 = -1e30f, l0 = 0.f, l1 = 0.f;

    FL_ISSUE(0, 0);
    CPA_COMMIT();

    for (int c = 0; c < nchunk; c++) {
        if (c + 1 < nchunk) FL_ISSUE(c + 1, (c + 1) & 1);
        CPA_COMMIT();
        CPA_WAIT1();
        __syncthreads();

        const uint32_t* stg = fsm + 9216 + (c & 1) * FSTGW;
        const uint32_t* sKh = stg;
        const uint32_t* sKl = stg + 2304;
        const uint32_t* sVh = stg + 4608;
        const uint32_t* sVl = stg + 6912;

        float s[8][4];
#pragma unroll
        for (int j = 0; j < 8; j++)
#pragma unroll
            for (int q = 0; q < 4; q++) s[j][q] = 0.f;

#pragma unroll
        for (int ks = 0; ks < 4; ks++) {
            uint32_t ah[4], al[4];
            int r = w * 16 + rA;
            int cc = 8 * ks + cA;
            ah[0] = sQh[r * 36 + cc];
            ah[1] = sQh[(r + 8) * 36 + cc];
            ah[2] = sQh[r * 36 + cc + 4];
            ah[3] = sQh[(r + 8) * 36 + cc + 4];
            al[0] = sQl[r * 36 + cc];
            al[1] = sQl[(r + 8) * 36 + cc];
            al[2] = sQl[r * 36 + cc + 4];
            al[3] = sQl[(r + 8) * 36 + cc + 4];
#pragma unroll
            for (int j = 0; j < 8; j++) {
                int n = j * 8 + rA;
                uint32_t bh0 = sKh[(8 * ks + cA) * 72 + n];
                uint32_t bh1 = sKh[(8 * ks + 4 + cA) * 72 + n];
                uint32_t bl0 = sKl[(8 * ks + cA) * 72 + n];
                uint32_t bl1 = sKl[(8 * ks + 4 + cA) * 72 + n];
                MMA16816(s[j], ah, bh0, bh1);
                MMA16816(s[j], ah, bl0, bl1);
                MMA16816(s[j], al, bh0, bh1);
            }
        }

        int cbase = c * 64;
        bool lastc = (cbase + 64 > m);
#pragma unroll
        for (int j = 0; j < 8; j++)
#pragma unroll
            for (int q = 0; q < 4; q++) {
                float v = s[j][q] * ATT_SCALE;
                if (lastc && (cbase + j * 8 + 2 * cA + (q & 1)) >= m) v = -1e30f;
                s[j][q] = v;
            }

        float mx0 = -1e30f, mx1 = -1e30f;
#pragma unroll
        for (int j = 0; j < 8; j++) {
            mx0 = fmaxf(mx0, fmaxf(s[j][0], s[j][1]));
            mx1 = fmaxf(mx1, fmaxf(s[j][2], s[j][3]));
        }
        mx0 = fmaxf(mx0, __shfl_xor_sync(0xffffffffu, mx0, 1));
        mx0 = fmaxf(mx0, __shfl_xor_sync(0xffffffffu, mx0, 2));
        mx1 = fmaxf(mx1, __shfl_xor_sync(0xffffffffu, mx1, 1));
        mx1 = fmaxf(mx1, __shfl_xor_sync(0xffffffffu, mx1, 2));
        float mn0 = fmaxf(mrun0, mx0), mn1 = fmaxf(mrun1, mx1);
        float sc0 = __expf(mrun0 - mn0), sc1 = __expf(mrun1 - mn1);
        mrun0 = mn0; mrun1 = mn1;

        float sum0 = 0.f, sum1 = 0.f;
#pragma unroll
        for (int j = 0; j < 8; j++) {
            s[j][0] = __expf(s[j][0] - mn0);
            s[j][1] = __expf(s[j][1] - mn0);
            s[j][2] = __expf(s[j][2] - mn1);
            s[j][3] = __expf(s[j][3] - mn1);
            sum0 += s[j][0] + s[j][1];
            sum1 += s[j][2] + s[j][3];
        }
        sum0 += __shfl_xor_sync(0xffffffffu, sum0, 1);
        sum0 += __shfl_xor_sync(0xffffffffu, sum0, 2);
        sum1 += __shfl_xor_sync(0xffffffffu, sum1, 1);
        sum1 += __shfl_xor_sync(0xffffffffu, sum1, 2);
        l0 = l0 * sc0 + sum0;
        l1 = l1 * sc1 + sum1;

#pragma unroll
        for (int nn = 0; nn < 8; nn++) {
            acc_o[nn][0] *= sc0; acc_o[nn][1] *= sc0;
            acc_o[nn][2] *= sc1; acc_o[nn][3] *= sc1;
        }

        uint32_t aph[4][4], apl[4][4];
#pragma unroll
        for (int kk = 0; kk < 4; kk++) {
            split2(s[2 * kk][0],     s[2 * kk][1],     aph[kk][0], apl[kk][0]);
            split2(s[2 * kk][2],     s[2 * kk][3],     aph[kk][1], apl[kk][1]);
            split2(s[2 * kk + 1][0], s[2 * kk + 1][1], aph[kk][2], apl[kk][2]);
            split2(s[2 * kk + 1][2], s[2 * kk + 1][3], aph[kk][3], apl[kk][3]);
        }

#pragma unroll
        for (int kk = 0; kk < 4; kk++) {
#pragma unroll
            for (int nn = 0; nn < 8; nn++) {
                int n = nn * 8 + rA;
                uint32_t vh0 = sVh[(8 * kk + cA) * 72 + n];
                uint32_t vh1 = sVh[(8 * kk + 4 + cA) * 72 + n];
                uint32_t vl0 = sVl[(8 * kk + cA) * 72 + n];
                uint32_t vl1 = sVl[(8 * kk + 4 + cA) * 72 + n];
                MMA16816(acc_o[nn], aph[kk], vh0, vh1);
                MMA16816(acc_o[nn], aph[kk], vl0, vl1);
                MMA16816(acc_o[nn], apl[kk], vh0, vh1);
            }
        }
        __syncthreads();
    }
#undef FL_ISSUE

    float inv0 = 1.f / l0, inv1 = 1.f / l1;
    size_t row0 = (size_t)b * NTOK + q0 + w * 16 + rA;
#pragma unroll
    for (int nn = 0; nn < 8; nn++) {
        int col = nn * 8 + 2 * cA;
        size_t w0 = row0 * 96 + (size_t)((hoff + col) >> 1);
        size_t w1 = (row0 + 8) * 96 + (size_t)((hoff + col) >> 1);
        uint32_t hi, lo;
        split2(acc_o[nn][0] * inv0, acc_o[nn][1] * inv0, hi, lo);
        xch[w0] = hi; xcl[w0] = lo;
        split2(acc_o[nn][2] * inv1, acc_o[nn][3] * inv1, hi, lo);
        xch[w1] = hi; xcl[w1] = lo;
    }
}

// ---------------- LayerNorm + exact GELU -> split bf16 -------------------------------
__device__ __forceinline__ float warpSum(float v) {
#pragma unroll
    for (int o = 16; o; o >>= 1) v += __shfl_xor_sync(0xffffffffu, v, o);
    return v;
}
__global__ void ln_gelu_kernel(const float* __restrict__ t, const float* __restrict__ g,
                               const float* __restrict__ bb,
                               __nv_bfloat16* __restrict__ th, __nv_bfloat16* __restrict__ tl) {
    size_t row = blockIdx.x;
    int tid = threadIdx.x;
    float v = t[row * NC + tid];
    __shared__ float sm[6];
    int lane = tid & 31, w = tid >> 5;
    float s = warpSum(v);
    if (lane == 0) sm[w] = s;
    __syncthreads();
    float mean = 0.f;
#pragma unroll
    for (int i = 0; i < 6; i++) mean += sm[i];
    mean *= (1.0f / 192.0f);
    float d = v - mean;
    __syncthreads();
    s = warpSum(d * d);
    if (lane == 0) sm[w] = s;
    __syncthreads();
    float var = 0.f;
#pragma unroll
    for (int i = 0; i < 6; i++) var += sm[i];
    var *= (1.0f / 192.0f);
    float y = d * rsqrtf(var + 1e-5f) * g[tid] + bb[tid];
    float r = y * normcdff(y);
    __nv_bfloat16 hi = __float2bfloat16(r);
    th[row * NC + tid] = hi;
    tl[row * NC + tid] = __float2bfloat16(r - __bfloat162float(hi));
}

// ---------------- host orchestration ---------------------------------------------------
extern "C" void kernel_launch(void* const* d_in, const int* in_sizes, int n_in,
                              void* d_out, int out_size)
{
    (void)in_sizes; (void)n_in; (void)out_size;
    const float* x    = (const float*)d_in[0];
    const float* q_w  = (const float*)d_in[1];
    const float* q_b  = (const float*)d_in[2];
    const float* kv_w = (const float*)d_in[3];
    const float* kv_b = (const float*)d_in[4];
    const float* sr_w[3] = {(const float*)d_in[5], (const float*)d_in[7], (const float*)d_in[9]};
    const float* sr_b[3] = {(const float*)d_in[6], (const float*)d_in[8], (const float*)d_in[10]};
    const float* ln_g[3] = {(const float*)d_in[11], (const float*)d_in[13], (const float*)d_in[15]};
    const float* ln_b[3] = {(const float*)d_in[12], (const float*)d_in[14], (const float*)d_in[16]};
    const float* lc_w[3] = {(const float*)d_in[17], (const float*)d_in[19], (const float*)d_in[21]};
    const float* lc_b[3] = {(const float*)d_in[18], (const float*)d_in[20], (const float*)d_in[22]};
    const float* nn1_w = (const float*)d_in[23];
    const float* nn1_b = (const float*)d_in[24];
    float* out = (float*)d_out;

    float *p_q, *p_t, *p_kv;
    __nv_bfloat16 *p_xh, *p_xl, *p_th, *p_tl, *p_qh, *p_ql;
    uint32_t *p_wp, *p_wq, *p_wkv, *p_wnn, *p_kvimg, *p_xch, *p_xcl;
    cudaGetSymbolAddress((void**)&p_q,    g_q);
    cudaGetSymbolAddress((void**)&p_t,    g_t);
    cudaGetSymbolAddress((void**)&p_kv,   g_kv);
    cudaGetSymbolAddress((void**)&p_xh,   g_xh);
    cudaGetSymbolAddress((void**)&p_xl,   g_xl);
    cudaGetSymbolAddress((void**)&p_th,   g_th);
    cudaGetSymbolAddress((void**)&p_tl,   g_tl);
    cudaGetSymbolAddress((void**)&p_wp,   g_wpack);
    cudaGetSymbolAddress((void**)&p_wq,   g_wq);
    cudaGetSymbolAddress((void**)&p_wkv,  g_wkv);
    cudaGetSymbolAddress((void**)&p_wnn,  g_wnn);
    cudaGetSymbolAddress((void**)&p_qh,   g_qh);
    cudaGetSymbolAddress((void**)&p_ql,   g_ql);
    cudaGetSymbolAddress((void**)&p_kvimg, g_kvimg);
    cudaGetSymbolAddress((void**)&p_xch,  g_xch);
    cudaGetSymbolAddress((void**)&p_xcl,  g_xcl);

    cudaFuncSetAttribute(conv_hmma_kernel, cudaFuncAttributeMaxDynamicSharedMemorySize,
                         2 * CSTGW * 4);
    cudaFuncSetAttribute(gemm_hmma_kernel, cudaFuncAttributeMaxDynamicSharedMemorySize,
                         2 * PSTGW * 4);
    cudaFuncSetAttribute(attn_flash_kernel, cudaFuncAttributeMaxDynamicSharedMemorySize,
                         (9216 + 2 * FSTGW) * 4);

    const int WPROJ = 12 * BIMG;

    prep_x_kernel<<<(NB * NTOK * NC + 255) / 256, 256>>>(x, p_xh, p_xl);
    prep_w_kernel<<<(WPROJ + 255) / 256, 256>>>(q_w, p_wq, 1);
    prep_w_kernel<<<(WPROJ + 255) / 256, 256>>>(kv_w, p_wkv, 1);
    prep_w_kernel<<<(WPROJ + 255) / 256, 256>>>(nn1_w, p_wnn, 1);

    gemm_hmma_kernel<<<dim3((NB * NTOK + 63) / 64, 2), 256, 2 * PSTGW * 4>>>(
        p_xh, p_xl, (const uint4*)p_wq, q_b, p_q, (long long)NB * NTOK, NC, NC);

    const int KS[3] = {8, 4, 2};
    for (int h = 0; h < 3; h++) {
        int k = KS[h];
        int side = 64 - k + 1;
        int m = side * side;
        int k2 = k * k;
        int nchunk = (m + 63) / 64;
        long long Bm = (long long)NB * m;

        prep_w_kernel<<<(k2 * WPROJ + 255) / 256, 256>>>(sr_w[h], p_wp, k2);
        conv_hmma_kernel<<<dim3((int)((Bm + 127) / 128), 2), 512, 2 * CSTGW * 4>>>(
            p_xh, p_xl, (const uint4*)p_wp, sr_b[h], p_t, k, side, m);
        ln_gelu_kernel<<<NB * m, 192>>>(p_t, ln_g[h], ln_b[h], p_th, p_tl);

        gemm_hmma_kernel<<<dim3((int)((Bm + 63) / 64), 2), 256, 2 * PSTGW * 4>>>(
            p_th, p_tl, (const uint4*)p_wkv, kv_b, p_kv, Bm, 128, 128);

        prep_q_kernel<<<(NB * NTOK * 64 + 255) / 256, 256>>>(p_q, p_qh, p_ql, h);

        pack_kv_kernel<<<(NB * nchunk * FSTGW + 255) / 256, 256>>>(
            p_kv, lc_w[h], lc_b[h], p_kvimg, m, nchunk, side);

        attn_flash_kernel<<<dim3(NTOK / 128, NB), 256, (9216 + 2 * FSTGW) * 4>>>(
            p_qh, p_ql, p_kvimg, p_xch, p_xcl, h * 64, m, nchunk);
    }

    gemm_hmma_kernel<<<dim3((NB * NTOK + 63) / 64, 2), 256, 2 * PSTGW * 4>>>(
        (const __nv_bfloat16*)p_xch, (const __nv_bfloat16*)p_xcl,
        (const uint4*)p_wnn, nn1_b, out, (long long)NB * NTOK, NC, NC);
}

// round 15
// speedup vs baseline: 1.2387x; 1.2387x over previous
#include <cuda_runtime.h>
#include <cuda_bf16.h>
#include <math.h>
#include <stdint.h>

#define NB   4
#define NTOK 4096
#define NC   192
#define MAXM 3969
#define BIMG 3456                        // B image words: 96 rows x 36 pitch
#define CSTGW 11520                      // stage words: Ah2304+Al2304+B0 3456+B1 3456
#define FSTGW 9216                       // flash stage words: kh/kl/vh/vl x 2304

static const float ATT_SCALE = 0.07216878364870323f; // 192^-0.5

// ---------------- scratch -------------------------------------------------------
__device__ float g_q[NB * NTOK * NC];
__device__ float g_t[(size_t)NB * MAXM * NC];
__device__ float g_kv[NB * MAXM * 128];
__device__ float g_vp[NB * MAXM * 64];
__device__ __nv_bfloat16 g_xh[NB * NTOK * NC];
__device__ __nv_bfloat16 g_xl[NB * NTOK * NC];
__device__ __nv_bfloat16 g_th[(size_t)NB * MAXM * NC];
__device__ __nv_bfloat16 g_tl[(size_t)NB * MAXM * NC];
__device__ uint32_t g_xch[NB * NTOK * 96];
__device__ uint32_t g_xcl[NB * NTOK * 96];
__device__ uint32_t g_wpack[768 * BIMG];
__device__ uint32_t g_wq[12 * BIMG];
__device__ uint32_t g_wkv[12 * BIMG];
__device__ uint32_t g_wnn[12 * BIMG];
__device__ __nv_bfloat16 g_qh[NB * NTOK * 64];
__device__ __nv_bfloat16 g_ql[NB * NTOK * 64];
__device__ uint32_t g_kvimg[NB * 63 * FSTGW];

// ---------------- helpers ---------------------------------------------------------
__device__ __forceinline__ uint32_t smem_u32(const void* p) {
    uint32_t a;
    asm("{ .reg .u64 t; cvta.to.shared.u64 t, %1; cvt.u32.u64 %0, t; }" : "=r"(a) : "l"(p));
    return a;
}
#define MMA16816(acc, a, b0, b1)                                                    \
    asm volatile("mma.sync.aligned.m16n8k16.row.col.f32.bf16.bf16.f32 "             \
        "{%0,%1,%2,%3}, {%4,%5,%6,%7}, {%8,%9}, {%0,%1,%2,%3};"                     \
        : "+f"((acc)[0]), "+f"((acc)[1]), "+f"((acc)[2]), "+f"((acc)[3])            \
        : "r"((a)[0]), "r"((a)[1]), "r"((a)[2]), "r"((a)[3]), "r"(b0), "r"(b1))
#define LDSM4(r0, r1, r2, r3, addr)                                                 \
    asm volatile("ldmatrix.sync.aligned.m8n8.x4.shared.b16 {%0,%1,%2,%3}, [%4];"    \
        : "=r"(r0), "=r"(r1), "=r"(r2), "=r"(r3) : "r"(addr))
#define LDSM2(r0, r1, addr)                                                         \
    asm volatile("ldmatrix.sync.aligned.m8n8.x2.shared.b16 {%0,%1}, [%2];"          \
        : "=r"(r0), "=r"(r1) : "r"(addr))
#define CPA16(dst, src)                                                             \
    asm volatile("cp.async.cg.shared.global [%0], [%1], 16;"                        \
        :: "r"(dst), "l"(src))
#define CPA_COMMIT() asm volatile("cp.async.commit_group;" ::: "memory")
#define CPA_WAIT1()  asm volatile("cp.async.wait_group 1;" ::: "memory")

__device__ __forceinline__ void split2(float a, float b, uint32_t& hi, uint32_t& lo) {
    __nv_bfloat16 ha = __float2bfloat16(a), hb = __float2bfloat16(b);
    float ra = a - __bfloat162float(ha);
    float rb = b - __bfloat162float(hb);
    __nv_bfloat16 la = __float2bfloat16(ra), lb = __float2bfloat16(rb);
    hi = ((uint32_t)*(unsigned short*)&hb << 16) | *(unsigned short*)&ha;
    lo = ((uint32_t)*(unsigned short*)&lb << 16) | *(unsigned short*)&la;
}

// ---------------- prep: split x into bf16 hi/lo -----------------------------------
__global__ void prep_x_kernel(const float* __restrict__ x, __nv_bfloat16* __restrict__ xh,
                              __nv_bfloat16* __restrict__ xl) {
    int i = blockIdx.x * 256 + threadIdx.x;
    if (i >= NB * NTOK * NC) return;
    float f = x[i];
    __nv_bfloat16 h = __float2bfloat16(f);
    xh[i] = h;
    xl[i] = __float2bfloat16(f - __bfloat162float(h));
}

// ---------------- prep: W -> n-major packed word images -----------------------------
__global__ void prep_w_kernel(const float* __restrict__ w, uint32_t* __restrict__ wp,
                              int k2) {
    int idx = blockIdx.x * 256 + threadIdx.x;
    int total = k2 * 12 * BIMG;
    if (idx >= total) return;
    int img = idx / BIMG, rem = idx % BIMG;
    int n = rem / 36, c2 = rem % 36;
    if (c2 >= 32) { wp[idx] = 0u; return; }
    int tap = img / 12, r = img % 12;
    int cb = r >> 2, r2 = r & 3;
    int cohalf = r2 >> 1, split = r2 & 1;
    int ci = cb * 64 + 2 * c2;
    int co = cohalf * 96 + n;
    float fe = w[((size_t)co * NC + ci) * k2 + tap];
    float fo = w[((size_t)co * NC + ci + 1) * k2 + tap];
    __nv_bfloat16 he = __float2bfloat16(fe), ho = __float2bfloat16(fo);
    __nv_bfloat16 ve = split ? __float2bfloat16(fe - __bfloat162float(he)) : he;
    __nv_bfloat16 vo = split ? __float2bfloat16(fo - __bfloat162float(ho)) : ho;
    uint32_t we = *(const unsigned short*)&ve;
    uint32_t wo = *(const unsigned short*)&vo;
    wp[idx] = (wo << 16) | we;
}

// ---------------- shared compute core (ldmatrix + MMA) ------------------------------
#define HMMA_GROUP_COMPUTE(soff)                                                     \
    _Pragma("unroll")                                                                \
    for (int ks = 0; ks < 4; ks++) {                                                 \
        uint32_t kb = (uint32_t)(ks * 32);                                           \
        uint32_t ah[4], ah2[4], al[4], al2[4];                                       \
        LDSM4(ah[0], ah[1], ah[2], ah[3], aoff0 + (soff) + kb);                      \
        LDSM4(ah2[0], ah2[1], ah2[2], ah2[3], aoff1 + (soff) + kb);                  \
        LDSM4(al[0], al[1], al[2], al[3], aoff0 + (soff) + 9216u + kb);              \
        LDSM4(al2[0], al2[1], al2[2], al2[3], aoff1 + (soff) + 9216u + kb);          \
        uint32_t wh[3][2], wl[3][2];                                                 \
        LDSM4(wh[0][0], wh[0][1], wh[1][0], wh[1][1], boff01 + (soff) + kb);         \
        LDSM2(wh[2][0], wh[2][1], boff2 + (soff) + kb);                              \
        LDSM4(wl[0][0], wl[0][1], wl[1][0], wl[1][1], boff01 + (soff) + 13824u + kb);\
        LDSM2(wl[2][0], wl[2][1], boff2 + (soff) + 13824u + kb);                     \
        _Pragma("unroll")                                                            \
        for (int j = 0; j < 3; j++) {                                                \
            MMA16816(acc[0][j], ah, wh[j][0], wh[j][1]);                             \
            MMA16816(acc[0][j], ah, wl[j][0], wl[j][1]);                             \
            MMA16816(acc[0][j], al, wh[j][0], wh[j][1]);                             \
            MMA16816(acc[1][j], ah2, wh[j][0], wh[j][1]);                            \
            MMA16816(acc[1][j], ah2, wl[j][0], wl[j][1]);                            \
            MMA16816(acc[1][j], al2, wh[j][0], wh[j][1]);                            \
        }                                                                            \
    }

// ---------------- conv: implicit GEMM, HMMA + ldmatrix, cp.async x2 (R13) ------------
__global__ void __launch_bounds__(256, 2) conv_hmma_kernel(
    const __nv_bfloat16* __restrict__ xh, const __nv_bfloat16* __restrict__ xl,
    const uint4* __restrict__ wp, const float* __restrict__ bias,
    float* __restrict__ out, int k, int side, int m)
{
    extern __shared__ uint32_t dsm[];

    int tid = threadIdx.x;
    int lane = tid & 31, wid = tid >> 5;
    int wm = wid & 1, wn = wid >> 1;
    long long Bm = (long long)NB * m;

    int arow = tid >> 2, aq = tid & 3;
    long long apx = (long long)blockIdx.x * 64 + arow;
    long long apxc = apx < Bm - 1 ? apx : Bm - 1;
    int ab = (int)(apxc / m), app = (int)(apxc % m);
    int aoy = app / side, aox = app % side;
    size_t axbase = (size_t)ab * NTOK * NC;
    int half = blockIdx.y;
    int rA = lane >> 2, cA = lane & 3;

    uint32_t smbase = smem_u32(dsm);
    uint32_t awd = smbase + (uint32_t)(arow * 36 + aq * 8) * 4;
    uint32_t bwd = smbase + 4608u * 4;

    int lrow = lane & 15, lcol = lane >> 4;
    uint32_t aoff0 = smbase + (uint32_t)((wm * 32 + lrow) * 144 + lcol * 16);
    uint32_t aoff1 = aoff0 + 16 * 144;
    int brow = (lane & 7) + ((lane & 16) ? 8 : 0);
    int bcolb = ((lane >> 3) & 1) * 16;
    uint32_t boff01 = smbase + 4608u * 4 + (uint32_t)((wn * 24 + brow) * 144 + bcolb);
    uint32_t boff2  = smbase + 4608u * 4 + (uint32_t)((wn * 24 + 16 + (lane & 7)) * 144
                                                      + bcolb);

    float acc[2][3][4];
#pragma unroll
    for (int i = 0; i < 2; i++)
#pragma unroll
        for (int j = 0; j < 3; j++)
#pragma unroll
            for (int q = 0; q < 4; q++) acc[i][j][q] = 0.f;

    int k2 = k * k;
    int ng = k2 * 3;

#define CONV_ISSUE(g, s) do {                                                        \
        int _tap = (g) / 3, _cb = (g) - _tap * 3;                                    \
        int _dy = _tap / k, _dx = _tap - _dy * k;                                    \
        size_t _aoff = axbase + (size_t)((aoy + _dy) * 64 + aox + _dx) * NC          \
                     + _cb * 64 + aq * 16;                                           \
        uint32_t _soff = (uint32_t)(s) * (CSTGW * 4);                                \
        const char* _gh = (const char*)(xh + _aoff);                                 \
        const char* _gl = (const char*)(xl + _aoff);                                 \
        CPA16(awd + _soff,      _gh);                                                \
        CPA16(awd + _soff + 16, _gh + 16);                                           \
        CPA16(awd + _soff + 2304u * 4,      _gl);                                    \
        CPA16(awd + _soff + 2304u * 4 + 16, _gl + 16);                               \
        int _imgb = (_tap * 3 + _cb) * 4 + half * 2;                                 \
        const char* _gb = (const char*)(wp + (size_t)_imgb * (BIMG / 4));            \
        _Pragma("unroll")                                                            \
        for (int _i = 0; _i < 7; _i++) {                                             \
            int _idx = tid + _i * 256;                                               \
            if (_idx < 1728) CPA16(bwd + _soff + _idx * 16, _gb + (size_t)_idx * 16);\
        }                                                                            \
    } while (0)

    CONV_ISSUE(0, 0);
    CPA_COMMIT();

    for (int g = 0; g < ng; g++) {
        if (g + 1 < ng) CONV_ISSUE(g + 1, (g + 1) & 1);
        CPA_COMMIT();
        CPA_WAIT1();
        __syncthreads();

        uint32_t soff = (uint32_t)(g & 1) * (CSTGW * 4);
        HMMA_GROUP_COMPUTE(soff);
        __syncthreads();
    }
#undef CONV_ISSUE

#pragma unroll
    for (int i = 0; i < 2; i++) {
        long long row0 = (long long)blockIdx.x * 64 + wm * 32 + i * 16 + rA;
#pragma unroll
        for (int j = 0; j < 3; j++) {
            int col = half * 96 + wn * 24 + j * 8 + 2 * cA;
            float b0 = bias[col], b1 = bias[col + 1];
            if (row0 < Bm) {
                float2 v = make_float2(acc[i][j][0] + b0, acc[i][j][1] + b1);
                *(float2*)&out[row0 * NC + col] = v;
            }
            if (row0 + 8 < Bm) {
                float2 v = make_float2(acc[i][j][2] + b0, acc[i][j][3] + b1);
                *(float2*)&out[(row0 + 8) * NC + col] = v;
            }
        }
    }
}

// ---------------- projection GEMM on HMMA + ldmatrix (R13) ---------------------------
__global__ void __launch_bounds__(256, 2) gemm_hmma_kernel(
    const __nv_bfloat16* __restrict__ Ah_g, const __nv_bfloat16* __restrict__ Al_g,
    const uint4* __restrict__ wimg, const float* __restrict__ bias,
    float* __restrict__ out, long long rows, int ldout, int Nout)
{
    extern __shared__ uint32_t dsm[];

    int tid = threadIdx.x;
    int lane = tid & 31, wid = tid >> 5;
    int wm = wid & 1, wn = wid >> 1;

    int arow = tid >> 2, aq = tid & 3;
    long long r = (long long)blockIdx.x * 64 + arow;
    long long rc = r < rows - 1 ? r : rows - 1;
    int half = blockIdx.y;
    int rA = lane >> 2, cA = lane & 3;

    uint32_t smbase = smem_u32(dsm);
    uint32_t awd = smbase + (uint32_t)(arow * 36 + aq * 8) * 4;
    uint32_t bwd = smbase + 4608u * 4;

    int lrow = lane & 15, lcol = lane >> 4;
    uint32_t aoff0 = smbase + (uint32_t)((wm * 32 + lrow) * 144 + lcol * 16);
    uint32_t aoff1 = aoff0 + 16 * 144;
    int brow = (lane & 7) + ((lane & 16) ? 8 : 0);
    int bcolb = ((lane >> 3) & 1) * 16;
    uint32_t boff01 = smbase + 4608u * 4 + (uint32_t)((wn * 24 + brow) * 144 + bcolb);
    uint32_t boff2  = smbase + 4608u * 4 + (uint32_t)((wn * 24 + 16 + (lane & 7)) * 144
                                                      + bcolb);

    float acc[2][3][4];
#pragma unroll
    for (int i = 0; i < 2; i++)
#pragma unroll
        for (int j = 0; j < 3; j++)
#pragma unroll
            for (int q = 0; q < 4; q++) acc[i][j][q] = 0.f;

#define PROJ_ISSUE(g, s) do {                                                        \
        size_t _aoff = (size_t)rc * NC + (g) * 64 + aq * 16;                         \
        uint32_t _soff = (uint32_t)(s) * (CSTGW * 4);                                \
        const char* _gh = (const char*)(Ah_g + _aoff);                               \
        const char* _gl = (const char*)(Al_g + _aoff);                               \
        CPA16(awd + _soff,      _gh);                                                \
        CPA16(awd + _soff + 16, _gh + 16);                                           \
        CPA16(awd + _soff + 2304u * 4,      _gl);                                    \
        CPA16(awd + _soff + 2304u * 4 + 16, _gl + 16);                               \
        int _imgb = (g) * 4 + half * 2;                                              \
        const char* _gb = (const char*)(wimg + (size_t)_imgb * (BIMG / 4));          \
        _Pragma("unroll")                                                            \
        for (int _i = 0; _i < 7; _i++) {                                             \
            int _idx = tid + _i * 256;                                               \
            if (_idx < 1728) CPA16(bwd + _soff + _idx * 16, _gb + (size_t)_idx * 16);\
        }                                                                            \
    } while (0)

    PROJ_ISSUE(0, 0);
    CPA_COMMIT();

    for (int g = 0; g < 3; g++) {
        if (g + 1 < 3) PROJ_ISSUE(g + 1, (g + 1) & 1);
        CPA_COMMIT();
        CPA_WAIT1();
        __syncthreads();

        uint32_t soff = (uint32_t)(g & 1) * (CSTGW * 4);
        HMMA_GROUP_COMPUTE(soff);
        __syncthreads();
    }
#undef PROJ_ISSUE

#pragma unroll
    for (int i = 0; i < 2; i++) {
        long long row0 = (long long)blockIdx.x * 64 + wm * 32 + i * 16 + rA;
#pragma unroll
        for (int j = 0; j < 3; j++) {
            int col = half * 96 + wn * 24 + j * 8 + 2 * cA;
            if (col >= Nout) continue;
            float b0 = bias[col], b1 = bias[col + 1];
            if (row0 < rows) {
                float2 v = make_float2(acc[i][j][0] + b0, acc[i][j][1] + b1);
                *(float2*)&out[row0 * ldout + col] = v;
            }
            if (row0 + 8 < rows) {
                float2 v = make_float2(acc[i][j][2] + b0, acc[i][j][3] + b1);
                *(float2*)&out[(row0 + 8) * ldout + col] = v;
            }
        }
    }
}

// ---------------- prep q split ------------------------------------------------------
__global__ void prep_q_kernel(const float* __restrict__ q, __nv_bfloat16* __restrict__ qh,
                              __nv_bfloat16* __restrict__ ql, int h) {
    int i = blockIdx.x * 256 + threadIdx.x;
    if (i >= NB * NTOK * 64) return;
    int c = i & 63;
    int row = i >> 6;
    float f = q[(size_t)row * NC + h * 64 + c];
    __nv_bfloat16 hi = __float2bfloat16(f);
    qh[i] = hi;
    ql[i] = __float2bfloat16(f - __bfloat162float(hi));
}

// ---------------- pack k + v' into per-chunk MMA image blocks (R13) ------------------
__global__ void pack_kv_kernel(const float* __restrict__ kv, const float* __restrict__ vp,
                               uint32_t* __restrict__ img, int m, int nchunk) {
    int idx = blockIdx.x * 256 + threadIdx.x;
    int total = NB * nchunk * FSTGW;
    if (idx >= total) return;
    int b = idx / (nchunk * FSTGW);
    int rem = idx % (nchunk * FSTGW);
    int c = rem / FSTGW;
    int r2 = rem % FSTGW;
    int sect = r2 / 2304;
    int r3 = r2 % 2304;
    int c2 = r3 / 72, n = r3 % 72;
    if (n >= 64) { img[idx] = 0u; return; }
    float f0, f1;
    if (sect < 2) {
        int mi = c * 64 + n;
        if (mi < m) {
            const float* kr = kv + ((size_t)b * m + mi) * 128;
            f0 = kr[2 * c2];
            f1 = kr[2 * c2 + 1];
        } else { f0 = f1 = 0.f; }
    } else {
        int k0 = c * 64 + 2 * c2;
        f0 = (k0 < m) ? vp[((size_t)b * m + k0) * 64 + n] : 0.f;
        f1 = (k0 + 1 < m) ? vp[((size_t)b * m + k0 + 1) * 64 + n] : 0.f;
    }
    uint32_t hi, lo;
    split2(f0, f1, hi, lo);
    img[idx] = (sect & 1) ? lo : hi;
}

// ---------------- fused flash attention: 64 q-rows per CTA (128 thr, 2 CTA/SM) -------
__global__ void __launch_bounds__(128, 2) attn_flash_kernel(
    const __nv_bfloat16* __restrict__ qh, const __nv_bfloat16* __restrict__ ql,
    const uint32_t* __restrict__ kvimg,
    uint32_t* __restrict__ xch, uint32_t* __restrict__ xcl,
    int hoff, int m, int nchunk)
{
    extern __shared__ uint32_t fsm[];
    uint32_t* sQh = fsm;              // 64*36
    uint32_t* sQl = fsm + 2304;       // 64*36
    // stages at fsm + 4608 + s*FSTGW

    int tid = threadIdx.x, lane = tid & 31, w = tid >> 5;   // 4 warps
    int rA = lane >> 2, cA = lane & 3;
    int b = blockIdx.y;
    int q0 = blockIdx.x * 64;

    uint32_t stg_b = smem_u32(fsm) + 4608u * 4;

    {   // q fill: 64 rows x 2 threads/row, 16 words each
        int arow = tid >> 1, ahalf = tid & 1;
        size_t off = ((size_t)b * NTOK + q0 + arow) * 64 + ahalf * 32;
        const uint4* sh = (const uint4*)(qh + off);
        const uint4* sl = (const uint4*)(ql + off);
        uint32_t* dh = sQh + arow * 36 + ahalf * 16;
        uint32_t* dl = sQl + arow * 36 + ahalf * 16;
#pragma unroll
        for (int j = 0; j < 4; j++) { *(uint4*)&dh[j * 4] = sh[j]; *(uint4*)&dl[j * 4] = sl[j]; }
    }

#define FL_ISSUE(c, s) do {                                                          \
        const char* _src = (const char*)(kvimg + ((size_t)b * nchunk + (c)) * FSTGW);\
        uint32_t _dst = stg_b + (uint32_t)(s) * (FSTGW * 4);                         \
        _Pragma("unroll")                                                            \
        for (int _t = 0; _t < 18; _t++) {                                            \
            int _idx = tid + _t * 128;                                               \
            CPA16(_dst + _idx * 16, _src + (size_t)_idx * 16);                       \
        }                                                                            \
    } while (0)

    float acc_o[8][4];
#pragma unroll
    for (int nn = 0; nn < 8; nn++)
#pragma unroll
        for (int q = 0; q < 4; q++) acc_o[nn][q] = 0.f;
    float mrun0 = -1e30f, mrun1 = -1e30f, l0 = 0.f, l1 = 0.f;

    FL_ISSUE(0, 0);
    CPA_COMMIT();

    for (int c = 0; c < nchunk; c++) {
        if (c + 1 < nchunk) FL_ISSUE(c + 1, (c + 1) & 1);
        CPA_COMMIT();
        CPA_WAIT1();
        __syncthreads();

        const uint32_t* stg = fsm + 4608 + (c & 1) * FSTGW;
        const uint32_t* sKh = stg;
        const uint32_t* sKl = stg + 2304;
        const uint32_t* sVh = stg + 4608;
        const uint32_t* sVl = stg + 6912;

        float s[8][4];
#pragma unroll
        for (int j = 0; j < 8; j++)
#pragma unroll
            for (int q = 0; q < 4; q++) s[j][q] = 0.f;

#pragma unroll
        for (int ks = 0; ks < 4; ks++) {
            uint32_t ah[4], al[4];
            int r = w * 16 + rA;
            int cc = 8 * ks + cA;
            ah[0] = sQh[r * 36 + cc];
            ah[1] = sQh[(r + 8) * 36 + cc];
            ah[2] = sQh[r * 36 + cc + 4];
            ah[3] = sQh[(r + 8) * 36 + cc + 4];
            al[0] = sQl[r * 36 + cc];
            al[1] = sQl[(r + 8) * 36 + cc];
            al[2] = sQl[r * 36 + cc + 4];
            al[3] = sQl[(r + 8) * 36 + cc + 4];
#pragma unroll
            for (int j = 0; j < 8; j++) {
                int n = j * 8 + rA;
                uint32_t bh0 = sKh[(8 * ks + cA) * 72 + n];
                uint32_t bh1 = sKh[(8 * ks + 4 + cA) * 72 + n];
                uint32_t bl0 = sKl[(8 * ks + cA) * 72 + n];
                uint32_t bl1 = sKl[(8 * ks + 4 + cA) * 72 + n];
                MMA16816(s[j], ah, bh0, bh1);
                MMA16816(s[j], ah, bl0, bl1);
                MMA16816(s[j], al, bh0, bh1);
            }
        }

        int cbase = c * 64;
        bool lastc = (cbase + 64 > m);
#pragma unroll
        for (int j = 0; j < 8; j++)
#pragma unroll
            for (int q = 0; q < 4; q++) {
                float v = s[j][q] * ATT_SCALE;
                if (lastc && (cbase + j * 8 + 2 * cA + (q & 1)) >= m) v = -1e30f;
                s[j][q] = v;
            }

        float mx0 = -1e30f, mx1 = -1e30f;
#pragma unroll
        for (int j = 0; j < 8; j++) {
            mx0 = fmaxf(mx0, fmaxf(s[j][0], s[j][1]));
            mx1 = fmaxf(mx1, fmaxf(s[j][2], s[j][3]));
        }
        mx0 = fmaxf(mx0, __shfl_xor_sync(0xffffffffu, mx0, 1));
        mx0 = fmaxf(mx0, __shfl_xor_sync(0xffffffffu, mx0, 2));
        mx1 = fmaxf(mx1, __shfl_xor_sync(0xffffffffu, mx1, 1));
        mx1 = fmaxf(mx1, __shfl_xor_sync(0xffffffffu, mx1, 2));
        float mn0 = fmaxf(mrun0, mx0), mn1 = fmaxf(mrun1, mx1);
        float sc0 = __expf(mrun0 - mn0), sc1 = __expf(mrun1 - mn1);
        mrun0 = mn0; mrun1 = mn1;

        float sum0 = 0.f, sum1 = 0.f;
#pragma unroll
        for (int j = 0; j < 8; j++) {
            s[j][0] = __expf(s[j][0] - mn0);
            s[j][1] = __expf(s[j][1] - mn0);
            s[j][2] = __expf(s[j][2] - mn1);
            s[j][3] = __expf(s[j][3] - mn1);
            sum0 += s[j][0] + s[j][1];
            sum1 += s[j][2] + s[j][3];
        }
        sum0 += __shfl_xor_sync(0xffffffffu, sum0, 1);
        sum0 += __shfl_xor_sync(0xffffffffu, sum0, 2);
        sum1 += __shfl_xor_sync(0xffffffffu, sum1, 1);
        sum1 += __shfl_xor_sync(0xffffffffu, sum1, 2);
        l0 = l0 * sc0 + sum0;
        l1 = l1 * sc1 + sum1;

#pragma unroll
        for (int nn = 0; nn < 8; nn++) {
            acc_o[nn][0] *= sc0; acc_o[nn][1] *= sc0;
            acc_o[nn][2] *= sc1; acc_o[nn][3] *= sc1;
        }

        uint32_t aph[4][4], apl[4][4];
#pragma unroll
        for (int kk = 0; kk < 4; kk++) {
            split2(s[2 * kk][0],     s[2 * kk][1],     aph[kk][0], apl[kk][0]);
            split2(s[2 * kk][2],     s[2 * kk][3],     aph[kk][1], apl[kk][1]);
            split2(s[2 * kk + 1][0], s[2 * kk + 1][1], aph[kk][2], apl[kk][2]);
            split2(s[2 * kk + 1][2], s[2 * kk + 1][3], aph[kk][3], apl[kk][3]);
        }

#pragma unroll
        for (int kk = 0; kk < 4; kk++) {
#pragma unroll
            for (int nn = 0; nn < 8; nn++) {
                int n = nn * 8 + rA;
                uint32_t vh0 = sVh[(8 * kk + cA) * 72 + n];
                uint32_t vh1 = sVh[(8 * kk + 4 + cA) * 72 + n];
                uint32_t vl0 = sVl[(8 * kk + cA) * 72 + n];
                uint32_t vl1 = sVl[(8 * kk + 4 + cA) * 72 + n];
                MMA16816(acc_o[nn], aph[kk], vh0, vh1);
                MMA16816(acc_o[nn], aph[kk], vl0, vl1);
                MMA16816(acc_o[nn], apl[kk], vh0, vh1);
            }
        }
        __syncthreads();
    }
#undef FL_ISSUE

    float inv0 = 1.f / l0, inv1 = 1.f / l1;
    size_t row0 = (size_t)b * NTOK + q0 + w * 16 + rA;
#pragma unroll
    for (int nn = 0; nn < 8; nn++) {
        int col = nn * 8 + 2 * cA;
        size_t w0 = row0 * 96 + (size_t)((hoff + col) >> 1);
        size_t w1 = (row0 + 8) * 96 + (size_t)((hoff + col) >> 1);
        uint32_t hi, lo;
        split2(acc_o[nn][0] * inv0, acc_o[nn][1] * inv0, hi, lo);
        xch[w0] = hi; xcl[w0] = lo;
        split2(acc_o[nn][2] * inv1, acc_o[nn][3] * inv1, hi, lo);
        xch[w1] = hi; xcl[w1] = lo;
    }
}

// ---------------- LayerNorm + exact GELU -> split bf16 -------------------------------
__device__ __forceinline__ float warpSum(float v) {
#pragma unroll
    for (int o = 16; o; o >>= 1) v += __shfl_xor_sync(0xffffffffu, v, o);
    return v;
}
__global__ void ln_gelu_kernel(const float* __restrict__ t, const float* __restrict__ g,
                               const float* __restrict__ bb,
                               __nv_bfloat16* __restrict__ th, __nv_bfloat16* __restrict__ tl) {
    size_t row = blockIdx.x;
    int tid = threadIdx.x;
    float v = t[row * NC + tid];
    __shared__ float sm[6];
    int lane = tid & 31, w = tid >> 5;
    float s = warpSum(v);
    if (lane == 0) sm[w] = s;
    __syncthreads();
    float mean = 0.f;
#pragma unroll
    for (int i = 0; i < 6; i++) mean += sm[i];
    mean *= (1.0f / 192.0f);
    float d = v - mean;
    __syncthreads();
    s = warpSum(d * d);
    if (lane == 0) sm[w] = s;
    __syncthreads();
    float var = 0.f;
#pragma unroll
    for (int i = 0; i < 6; i++) var += sm[i];
    var *= (1.0f / 192.0f);
    float y = d * rsqrtf(var + 1e-5f) * g[tid] + bb[tid];
    float r = y * normcdff(y);
    __nv_bfloat16 hi = __float2bfloat16(r);
    th[row * NC + tid] = hi;
    tl[row * NC + tid] = __float2bfloat16(r - __bfloat162float(hi));
}

// ---------------- depthwise 3x3 on v, residual add (R13) -----------------------------
__global__ void dwconv_kernel(const float* __restrict__ kv, const float* __restrict__ lw,
                              const float* __restrict__ lb, float* __restrict__ vp,
                              int side, int m)
{
    long long idx = (long long)blockIdx.x * 256 + threadIdx.x;
    long long total = (long long)NB * m * 64;
    if (idx >= total) return;
    int hd = (int)(idx & 63);
    long long pm = idx >> 6;
    int p = (int)(pm % m);
    int b = (int)(pm / m);
    int y = p / side, x = p % side;
    const float* vbase = kv + (size_t)b * m * 128 + 64 + hd;
    float s = lb[hd];
#pragma unroll
    for (int dy = 0; dy < 3; dy++) {
        int yy = y + dy - 1;
        if (yy < 0 || yy >= side) continue;
#pragma unroll
        for (int dx = 0; dx < 3; dx++) {
            int xx = x + dx - 1;
            if (xx < 0 || xx >= side) continue;
            s += lw[hd * 9 + dy * 3 + dx] * vbase[(size_t)(yy * side + xx) * 128];
        }
    }
    vp[idx] = vbase[(size_t)p * 128] + s;
}

// ---------------- host orchestration ---------------------------------------------------
extern "C" void kernel_launch(void* const* d_in, const int* in_sizes, int n_in,
                              void* d_out, int out_size)
{
    (void)in_sizes; (void)n_in; (void)out_size;
    const float* x    = (const float*)d_in[0];
    const float* q_w  = (const float*)d_in[1];
    const float* q_b  = (const float*)d_in[2];
    const float* kv_w = (const float*)d_in[3];
    const float* kv_b = (const float*)d_in[4];
    const float* sr_w[3] = {(const float*)d_in[5], (const float*)d_in[7], (const float*)d_in[9]};
    const float* sr_b[3] = {(const float*)d_in[6], (const float*)d_in[8], (const float*)d_in[10]};
    const float* ln_g[3] = {(const float*)d_in[11], (const float*)d_in[13], (const float*)d_in[15]};
    const float* ln_b[3] = {(const float*)d_in[12], (const float*)d_in[14], (const float*)d_in[16]};
    const float* lc_w[3] = {(const float*)d_in[17], (const float*)d_in[19], (const float*)d_in[21]};
    const float* lc_b[3] = {(const float*)d_in[18], (const float*)d_in[20], (const float*)d_in[22]};
    const float* nn1_w = (const float*)d_in[23];
    const float* nn1_b = (const float*)d_in[24];
    float* out = (float*)d_out;

    float *p_q, *p_t, *p_kv, *p_vp;
    __nv_bfloat16 *p_xh, *p_xl, *p_th, *p_tl, *p_qh, *p_ql;
    uint32_t *p_wp, *p_wq, *p_wkv, *p_wnn, *p_kvimg, *p_xch, *p_xcl;
    cudaGetSymbolAddress((void**)&p_q,    g_q);
    cudaGetSymbolAddress((void**)&p_t,    g_t);
    cudaGetSymbolAddress((void**)&p_kv,   g_kv);
    cudaGetSymbolAddress((void**)&p_vp,   g_vp);
    cudaGetSymbolAddress((void**)&p_xh,   g_xh);
    cudaGetSymbolAddress((void**)&p_xl,   g_xl);
    cudaGetSymbolAddress((void**)&p_th,   g_th);
    cudaGetSymbolAddress((void**)&p_tl,   g_tl);
    cudaGetSymbolAddress((void**)&p_wp,   g_wpack);
    cudaGetSymbolAddress((void**)&p_wq,   g_wq);
    cudaGetSymbolAddress((void**)&p_wkv,  g_wkv);
    cudaGetSymbolAddress((void**)&p_wnn,  g_wnn);
    cudaGetSymbolAddress((void**)&p_qh,   g_qh);
    cudaGetSymbolAddress((void**)&p_ql,   g_ql);
    cudaGetSymbolAddress((void**)&p_kvimg, g_kvimg);
    cudaGetSymbolAddress((void**)&p_xch,  g_xch);
    cudaGetSymbolAddress((void**)&p_xcl,  g_xcl);

    cudaFuncSetAttribute(conv_hmma_kernel, cudaFuncAttributeMaxDynamicSharedMemorySize,
                         2 * CSTGW * 4);
    cudaFuncSetAttribute(gemm_hmma_kernel, cudaFuncAttributeMaxDynamicSharedMemorySize,
                         2 * CSTGW * 4);
    cudaFuncSetAttribute(attn_flash_kernel, cudaFuncAttributeMaxDynamicSharedMemorySize,
                         (4608 + 2 * FSTGW) * 4);

    const int WPROJ = 12 * BIMG;

    prep_x_kernel<<<(NB * NTOK * NC + 255) / 256, 256>>>(x, p_xh, p_xl);
    prep_w_kernel<<<(WPROJ + 255) / 256, 256>>>(q_w, p_wq, 1);
    prep_w_kernel<<<(WPROJ + 255) / 256, 256>>>(kv_w, p_wkv, 1);
    prep_w_kernel<<<(WPROJ + 255) / 256, 256>>>(nn1_w, p_wnn, 1);

    gemm_hmma_kernel<<<dim3((NB * NTOK + 63) / 64, 2), 256, 2 * CSTGW * 4>>>(
        p_xh, p_xl, (const uint4*)p_wq, q_b, p_q, (long long)NB * NTOK, NC, NC);

    const int KS[3] = {8, 4, 2};
    for (int h = 0; h < 3; h++) {
        int k = KS[h];
        int side = 64 - k + 1;
        int m = side * side;
        int k2 = k * k;
        int nchunk = (m + 63) / 64;
        long long Bm = (long long)NB * m;

        prep_w_kernel<<<(k2 * WPROJ + 255) / 256, 256>>>(sr_w[h], p_wp, k2);
        conv_hmma_kernel<<<dim3((int)((Bm + 63) / 64), 2), 256, 2 * CSTGW * 4>>>(
            p_xh, p_xl, (const uint4*)p_wp, sr_b[h], p_t, k, side, m);
        ln_gelu_kernel<<<NB * m, 192>>>(p_t, ln_g[h], ln_b[h], p_th, p_tl);

        gemm_hmma_kernel<<<dim3((int)((Bm + 63) / 64), 2), 256, 2 * CSTGW * 4>>>(
            p_th, p_tl, (const uint4*)p_wkv, kv_b, p_kv, Bm, 128, 128);

        prep_q_kernel<<<(NB * NTOK * 64 + 255) / 256, 256>>>(p_q, p_qh, p_ql, h);

        dwconv_kernel<<<(int)(((long long)NB * m * 64 + 255) / 256), 256>>>(
            p_kv, lc_w[h], lc_b[h], p_vp, side, m);
        pack_kv_kernel<<<(NB * nchunk * FSTGW + 255) / 256, 256>>>(
            p_kv, p_vp, p_kvimg, m, nchunk);

        attn_flash_kernel<<<dim3(NTOK / 64, NB), 128, (4608 + 2 * FSTGW) * 4>>>(
            p_qh, p_ql, p_kvimg, p_xch, p_xcl, h * 64, m, nchunk);
    }

    gemm_hmma_kernel<<<dim3((NB * NTOK + 63) / 64, 2), 256, 2 * CSTGW * 4>>>(
        (const __nv_bfloat16*)p_xch, (const __nv_bfloat16*)p_xcl,
        (const uint4*)p_wnn, nn1_b, out, (long long)NB * NTOK, NC, NC);
}

// round 16
// speedup vs baseline: 1.2456x; 1.0056x over previous
#include <cuda_runtime.h>
#include <cuda_bf16.h>
#include <math.h>
#include <stdint.h>

#define NB   4
#define NTOK 4096
#define NC   192
#define MAXM 3969
#define BIMG 3456                        // B image words: 96 rows x 36 pitch
#define CSTGW 11520                      // stage words: Ah2304+Al2304+B0 3456+B1 3456
#define FSTGW 9216                       // flash stage words: kh/kl/vh/vl x 2304

static const float ATT_SCALE = 0.07216878364870323f; // 192^-0.5

// ---------------- scratch -------------------------------------------------------
__device__ float g_t[(size_t)NB * MAXM * NC];
__device__ float g_kv[NB * MAXM * 128];
__device__ float g_vp[NB * MAXM * 64];
__device__ __nv_bfloat16 g_xh[NB * NTOK * NC];
__device__ __nv_bfloat16 g_xl[NB * NTOK * NC];
__device__ __nv_bfloat16 g_th[(size_t)NB * MAXM * NC];
__device__ __nv_bfloat16 g_tl[(size_t)NB * MAXM * NC];
__device__ uint32_t g_xch[NB * NTOK * 96];
__device__ uint32_t g_xcl[NB * NTOK * 96];
__device__ uint32_t g_wpack[768 * BIMG];
__device__ uint32_t g_wq[12 * BIMG];
__device__ uint32_t g_wkv[12 * BIMG];
__device__ uint32_t g_wnn[12 * BIMG];
__device__ uint32_t g_qs_h[3 * NB * NTOK * 32];   // per-head split q (word pairs)
__device__ uint32_t g_qs_l[3 * NB * NTOK * 32];
__device__ uint32_t g_kvimg[NB * 63 * FSTGW];

// ---------------- helpers ---------------------------------------------------------
__device__ __forceinline__ uint32_t smem_u32(const void* p) {
    uint32_t a;
    asm("{ .reg .u64 t; cvta.to.shared.u64 t, %1; cvt.u32.u64 %0, t; }" : "=r"(a) : "l"(p));
    return a;
}
#define MMA16816(acc, a, b0, b1)                                                    \
    asm volatile("mma.sync.aligned.m16n8k16.row.col.f32.bf16.bf16.f32 "             \
        "{%0,%1,%2,%3}, {%4,%5,%6,%7}, {%8,%9}, {%0,%1,%2,%3};"                     \
        : "+f"((acc)[0]), "+f"((acc)[1]), "+f"((acc)[2]), "+f"((acc)[3])            \
        : "r"((a)[0]), "r"((a)[1]), "r"((a)[2]), "r"((a)[3]), "r"(b0), "r"(b1))
#define LDSM4(r0, r1, r2, r3, addr)                                                 \
    asm volatile("ldmatrix.sync.aligned.m8n8.x4.shared.b16 {%0,%1,%2,%3}, [%4];"    \
        : "=r"(r0), "=r"(r1), "=r"(r2), "=r"(r3) : "r"(addr))
#define LDSM2(r0, r1, addr)                                                         \
    asm volatile("ldmatrix.sync.aligned.m8n8.x2.shared.b16 {%0,%1}, [%2];"          \
        : "=r"(r0), "=r"(r1) : "r"(addr))
#define CPA16(dst, src)                                                             \
    asm volatile("cp.async.cg.shared.global [%0], [%1], 16;"                        \
        :: "r"(dst), "l"(src))
#define CPA_COMMIT() asm volatile("cp.async.commit_group;" ::: "memory")
#define CPA_WAIT1()  asm volatile("cp.async.wait_group 1;" ::: "memory")

__device__ __forceinline__ void split2(float a, float b, uint32_t& hi, uint32_t& lo) {
    __nv_bfloat16 ha = __float2bfloat16(a), hb = __float2bfloat16(b);
    float ra = a - __bfloat162float(ha);
    float rb = b - __bfloat162float(hb);
    __nv_bfloat16 la = __float2bfloat16(ra), lb = __float2bfloat16(rb);
    hi = ((uint32_t)*(unsigned short*)&hb << 16) | *(unsigned short*)&ha;
    lo = ((uint32_t)*(unsigned short*)&lb << 16) | *(unsigned short*)&la;
}

// ---------------- prep: split x into bf16 hi/lo -----------------------------------
__global__ void prep_x_kernel(const float* __restrict__ x, __nv_bfloat16* __restrict__ xh,
                              __nv_bfloat16* __restrict__ xl) {
    int i = blockIdx.x * 256 + threadIdx.x;
    if (i >= NB * NTOK * NC) return;
    float f = x[i];
    __nv_bfloat16 h = __float2bfloat16(f);
    xh[i] = h;
    xl[i] = __float2bfloat16(f - __bfloat162float(h));
}

// ---------------- prep: W -> n-major packed word images -----------------------------
__global__ void prep_w_kernel(const float* __restrict__ w, uint32_t* __restrict__ wp,
                              int k2) {
    int idx = blockIdx.x * 256 + threadIdx.x;
    int total = k2 * 12 * BIMG;
    if (idx >= total) return;
    int img = idx / BIMG, rem = idx % BIMG;
    int n = rem / 36, c2 = rem % 36;
    if (c2 >= 32) { wp[idx] = 0u; return; }
    int tap = img / 12, r = img % 12;
    int cb = r >> 2, r2 = r & 3;
    int cohalf = r2 >> 1, split = r2 & 1;
    int ci = cb * 64 + 2 * c2;
    int co = cohalf * 96 + n;
    float fe = w[((size_t)co * NC + ci) * k2 + tap];
    float fo = w[((size_t)co * NC + ci + 1) * k2 + tap];
    __nv_bfloat16 he = __float2bfloat16(fe), ho = __float2bfloat16(fo);
    __nv_bfloat16 ve = split ? __float2bfloat16(fe - __bfloat162float(he)) : he;
    __nv_bfloat16 vo = split ? __float2bfloat16(fo - __bfloat162float(ho)) : ho;
    uint32_t we = *(const unsigned short*)&ve;
    uint32_t wo = *(const unsigned short*)&vo;
    wp[idx] = (wo << 16) | we;
}

// ---------------- shared compute core (ldmatrix + MMA) ------------------------------
#define HMMA_GROUP_COMPUTE(soff)                                                     \
    _Pragma("unroll")                                                                \
    for (int ks = 0; ks < 4; ks++) {                                                 \
        uint32_t kb = (uint32_t)(ks * 32);                                           \
        uint32_t ah[4], ah2[4], al[4], al2[4];                                       \
        LDSM4(ah[0], ah[1], ah[2], ah[3], aoff0 + (soff) + kb);                      \
        LDSM4(ah2[0], ah2[1], ah2[2], ah2[3], aoff1 + (soff) + kb);                  \
        LDSM4(al[0], al[1], al[2], al[3], aoff0 + (soff) + 9216u + kb);              \
        LDSM4(al2[0], al2[1], al2[2], al2[3], aoff1 + (soff) + 9216u + kb);          \
        uint32_t wh[3][2], wl[3][2];                                                 \
        LDSM4(wh[0][0], wh[0][1], wh[1][0], wh[1][1], boff01 + (soff) + kb);         \
        LDSM2(wh[2][0], wh[2][1], boff2 + (soff) + kb);                              \
        LDSM4(wl[0][0], wl[0][1], wl[1][0], wl[1][1], boff01 + (soff) + 13824u + kb);\
        LDSM2(wl[2][0], wl[2][1], boff2 + (soff) + 13824u + kb);                     \
        _Pragma("unroll")                                                            \
        for (int j = 0; j < 3; j++) {                                                \
            MMA16816(acc[0][j], ah, wh[j][0], wh[j][1]);                             \
            MMA16816(acc[0][j], ah, wl[j][0], wl[j][1]);                             \
            MMA16816(acc[0][j], al, wh[j][0], wh[j][1]);                             \
            MMA16816(acc[1][j], ah2, wh[j][0], wh[j][1]);                            \
            MMA16816(acc[1][j], ah2, wl[j][0], wl[j][1]);                            \
            MMA16816(acc[1][j], al2, wh[j][0], wh[j][1]);                            \
        }                                                                            \
    }

// ---------------- conv: implicit GEMM, HMMA + ldmatrix, cp.async x2 ------------------
__global__ void __launch_bounds__(256, 2) conv_hmma_kernel(
    const __nv_bfloat16* __restrict__ xh, const __nv_bfloat16* __restrict__ xl,
    const uint4* __restrict__ wp, const float* __restrict__ bias,
    float* __restrict__ out, int k, int side, int m)
{
    extern __shared__ uint32_t dsm[];

    int tid = threadIdx.x;
    int lane = tid & 31, wid = tid >> 5;
    int wm = wid & 1, wn = wid >> 1;
    long long Bm = (long long)NB * m;

    int arow = tid >> 2, aq = tid & 3;
    long long apx = (long long)blockIdx.x * 64 + arow;
    long long apxc = apx < Bm - 1 ? apx : Bm - 1;
    int ab = (int)(apxc / m), app = (int)(apxc % m);
    int aoy = app / side, aox = app % side;
    size_t axbase = (size_t)ab * NTOK * NC;
    int half = blockIdx.y;
    int rA = lane >> 2, cA = lane & 3;

    uint32_t smbase = smem_u32(dsm);
    uint32_t awd = smbase + (uint32_t)(arow * 36 + aq * 8) * 4;
    uint32_t bwd = smbase + 4608u * 4;

    int lrow = lane & 15, lcol = lane >> 4;
    uint32_t aoff0 = smbase + (uint32_t)((wm * 32 + lrow) * 144 + lcol * 16);
    uint32_t aoff1 = aoff0 + 16 * 144;
    int brow = (lane & 7) + ((lane & 16) ? 8 : 0);
    int bcolb = ((lane >> 3) & 1) * 16;
    uint32_t boff01 = smbase + 4608u * 4 + (uint32_t)((wn * 24 + brow) * 144 + bcolb);
    uint32_t boff2  = smbase + 4608u * 4 + (uint32_t)((wn * 24 + 16 + (lane & 7)) * 144
                                                      + bcolb);

    float acc[2][3][4];
#pragma unroll
    for (int i = 0; i < 2; i++)
#pragma unroll
        for (int j = 0; j < 3; j++)
#pragma unroll
            for (int q = 0; q < 4; q++) acc[i][j][q] = 0.f;

    int k2 = k * k;
    int ng = k2 * 3;

#define CONV_ISSUE(g, s) do {                                                        \
        int _tap = (g) / 3, _cb = (g) - _tap * 3;                                    \
        int _dy = _tap / k, _dx = _tap - _dy * k;                                    \
        size_t _aoff = axbase + (size_t)((aoy + _dy) * 64 + aox + _dx) * NC          \
                     + _cb * 64 + aq * 16;                                           \
        uint32_t _soff = (uint32_t)(s) * (CSTGW * 4);                                \
        const char* _gh = (const char*)(xh + _aoff);                                 \
        const char* _gl = (const char*)(xl + _aoff);                                 \
        CPA16(awd + _soff,      _gh);                                                \
        CPA16(awd + _soff + 16, _gh + 16);                                           \
        CPA16(awd + _soff + 2304u * 4,      _gl);                                    \
        CPA16(awd + _soff + 2304u * 4 + 16, _gl + 16);                               \
        int _imgb = (_tap * 3 + _cb) * 4 + half * 2;                                 \
        const char* _gb = (const char*)(wp + (size_t)_imgb * (BIMG / 4));            \
        _Pragma("unroll")                                                            \
        for (int _i = 0; _i < 7; _i++) {                                             \
            int _idx = tid + _i * 256;                                               \
            if (_idx < 1728) CPA16(bwd + _soff + _idx * 16, _gb + (size_t)_idx * 16);\
        }                                                                            \
    } while (0)

    CONV_ISSUE(0, 0);
    CPA_COMMIT();

    for (int g = 0; g < ng; g++) {
        if (g + 1 < ng) CONV_ISSUE(g + 1, (g + 1) & 1);
        CPA_COMMIT();
        CPA_WAIT1();
        __syncthreads();

        uint32_t soff = (uint32_t)(g & 1) * (CSTGW * 4);
        HMMA_GROUP_COMPUTE(soff);
        __syncthreads();
    }
#undef CONV_ISSUE

#pragma unroll
    for (int i = 0; i < 2; i++) {
        long long row0 = (long long)blockIdx.x * 64 + wm * 32 + i * 16 + rA;
#pragma unroll
        for (int j = 0; j < 3; j++) {
            int col = half * 96 + wn * 24 + j * 8 + 2 * cA;
            float b0 = bias[col], b1 = bias[col + 1];
            if (row0 < Bm) {
                float2 v = make_float2(acc[i][j][0] + b0, acc[i][j][1] + b1);
                *(float2*)&out[row0 * NC + col] = v;
            }
            if (row0 + 8 < Bm) {
                float2 v = make_float2(acc[i][j][2] + b0, acc[i][j][3] + b1);
                *(float2*)&out[(row0 + 8) * NC + col] = v;
            }
        }
    }
}

// ---------------- projection GEMM on HMMA + ldmatrix ---------------------------------
// If qs_h != nullptr: write split bf16 word-pairs in per-head layout
// word index = ((col/64)*rows + row) * 32 + (col%64)/2. Else: fp32 out (+bias).
__global__ void __launch_bounds__(256, 2) gemm_hmma_kernel(
    const __nv_bfloat16* __restrict__ Ah_g, const __nv_bfloat16* __restrict__ Al_g,
    const uint4* __restrict__ wimg, const float* __restrict__ bias,
    float* __restrict__ out, uint32_t* __restrict__ qs_h, uint32_t* __restrict__ qs_l,
    long long rows, int ldout, int Nout)
{
    extern __shared__ uint32_t dsm[];

    int tid = threadIdx.x;
    int lane = tid & 31, wid = tid >> 5;
    int wm = wid & 1, wn = wid >> 1;

    int arow = tid >> 2, aq = tid & 3;
    long long r = (long long)blockIdx.x * 64 + arow;
    long long rc = r < rows - 1 ? r : rows - 1;
    int half = blockIdx.y;
    int rA = lane >> 2, cA = lane & 3;

    uint32_t smbase = smem_u32(dsm);
    uint32_t awd = smbase + (uint32_t)(arow * 36 + aq * 8) * 4;
    uint32_t bwd = smbase + 4608u * 4;

    int lrow = lane & 15, lcol = lane >> 4;
    uint32_t aoff0 = smbase + (uint32_t)((wm * 32 + lrow) * 144 + lcol * 16);
    uint32_t aoff1 = aoff0 + 16 * 144;
    int brow = (lane & 7) + ((lane & 16) ? 8 : 0);
    int bcolb = ((lane >> 3) & 1) * 16;
    uint32_t boff01 = smbase + 4608u * 4 + (uint32_t)((wn * 24 + brow) * 144 + bcolb);
    uint32_t boff2  = smbase + 4608u * 4 + (uint32_t)((wn * 24 + 16 + (lane & 7)) * 144
                                                      + bcolb);

    float acc[2][3][4];
#pragma unroll
    for (int i = 0; i < 2; i++)
#pragma unroll
        for (int j = 0; j < 3; j++)
#pragma unroll
            for (int q = 0; q < 4; q++) acc[i][j][q] = 0.f;

#define PROJ_ISSUE(g, s) do {                                                        \
        size_t _aoff = (size_t)rc * NC + (g) * 64 + aq * 16;                         \
        uint32_t _soff = (uint32_t)(s) * (CSTGW * 4);                                \
        const char* _gh = (const char*)(Ah_g + _aoff);                               \
        const char* _gl = (const char*)(Al_g + _aoff);                               \
        CPA16(awd + _soff,      _gh);                                                \
        CPA16(awd + _soff + 16, _gh + 16);                                           \
        CPA16(awd + _soff + 2304u * 4,      _gl);                                    \
        CPA16(awd + _soff + 2304u * 4 + 16, _gl + 16);                               \
        int _imgb = (g) * 4 + half * 2;                                              \
        const char* _gb = (const char*)(wimg + (size_t)_imgb * (BIMG / 4));          \
        _Pragma("unroll")                                                            \
        for (int _i = 0; _i < 7; _i++) {                                             \
            int _idx = tid + _i * 256;                                               \
            if (_idx < 1728) CPA16(bwd + _soff + _idx * 16, _gb + (size_t)_idx * 16);\
        }                                                                            \
    } while (0)

    PROJ_ISSUE(0, 0);
    CPA_COMMIT();

    for (int g = 0; g < 3; g++) {
        if (g + 1 < 3) PROJ_ISSUE(g + 1, (g + 1) & 1);
        CPA_COMMIT();
        CPA_WAIT1();
        __syncthreads();

        uint32_t soff = (uint32_t)(g & 1) * (CSTGW * 4);
        HMMA_GROUP_COMPUTE(soff);
        __syncthreads();
    }
#undef PROJ_ISSUE

#pragma unroll
    for (int i = 0; i < 2; i++) {
        long long row0 = (long long)blockIdx.x * 64 + wm * 32 + i * 16 + rA;
#pragma unroll
        for (int j = 0; j < 3; j++) {
            int col = half * 96 + wn * 24 + j * 8 + 2 * cA;
            if (col >= Nout) continue;
            float b0 = bias[col], b1 = bias[col + 1];
            if (qs_h) {
                // split bf16 per-head output (q projection)
                size_t wbase = ((size_t)(col / 64) * rows) * 32 + (size_t)((col % 64) >> 1);
                uint32_t hi, lo;
                if (row0 < rows) {
                    split2(acc[i][j][0] + b0, acc[i][j][1] + b1, hi, lo);
                    qs_h[wbase + (size_t)row0 * 32] = hi;
                    qs_l[wbase + (size_t)row0 * 32] = lo;
                }
                if (row0 + 8 < rows) {
                    split2(acc[i][j][2] + b0, acc[i][j][3] + b1, hi, lo);
                    qs_h[wbase + (size_t)(row0 + 8) * 32] = hi;
                    qs_l[wbase + (size_t)(row0 + 8) * 32] = lo;
                }
            } else {
                if (row0 < rows) {
                    float2 v = make_float2(acc[i][j][0] + b0, acc[i][j][1] + b1);
                    *(float2*)&out[row0 * ldout + col] = v;
                }
                if (row0 + 8 < rows) {
                    float2 v = make_float2(acc[i][j][2] + b0, acc[i][j][3] + b1);
                    *(float2*)&out[(row0 + 8) * ldout + col] = v;
                }
            }
        }
    }
}

// ---------------- pack k + v' into per-chunk MMA image blocks ------------------------
__global__ void pack_kv_kernel(const float* __restrict__ kv, const float* __restrict__ vp,
                               uint32_t* __restrict__ img, int m, int nchunk) {
    int idx = blockIdx.x * 256 + threadIdx.x;
    int total = NB * nchunk * FSTGW;
    if (idx >= total) return;
    int b = idx / (nchunk * FSTGW);
    int rem = idx % (nchunk * FSTGW);
    int c = rem / FSTGW;
    int r2 = rem % FSTGW;
    int sect = r2 / 2304;
    int r3 = r2 % 2304;
    int c2 = r3 / 72, n = r3 % 72;
    if (n >= 64) { img[idx] = 0u; return; }
    float f0, f1;
    if (sect < 2) {
        int mi = c * 64 + n;
        if (mi < m) {
            const float* kr = kv + ((size_t)b * m + mi) * 128;
            f0 = kr[2 * c2];
            f1 = kr[2 * c2 + 1];
        } else { f0 = f1 = 0.f; }
    } else {
        int k0 = c * 64 + 2 * c2;
        f0 = (k0 < m) ? vp[((size_t)b * m + k0) * 64 + n] : 0.f;
        f1 = (k0 + 1 < m) ? vp[((size_t)b * m + k0 + 1) * 64 + n] : 0.f;
    }
    uint32_t hi, lo;
    split2(f0, f1, hi, lo);
    img[idx] = (sect & 1) ? lo : hi;
}

// ---------------- fused flash attention: 64 q-rows per CTA (128 thr, 2 CTA/SM) -------
__global__ void __launch_bounds__(128, 2) attn_flash_kernel(
    const uint32_t* __restrict__ qsh, const uint32_t* __restrict__ qsl,
    const uint32_t* __restrict__ kvimg,
    uint32_t* __restrict__ xch, uint32_t* __restrict__ xcl,
    int hoff, int m, int nchunk)
{
    extern __shared__ uint32_t fsm[];
    uint32_t* sQh = fsm;              // 64*36
    uint32_t* sQl = fsm + 2304;       // 64*36

    int tid = threadIdx.x, lane = tid & 31, w = tid >> 5;
    int rA = lane >> 2, cA = lane & 3;
    int b = blockIdx.y;
    int q0 = blockIdx.x * 64;

    uint32_t stg_b = smem_u32(fsm) + 4608u * 4;

    {   // q fill: 64 rows x 2 threads/row, 16 words each (word layout, 32 words/row)
        int arow = tid >> 1, ahalf = tid & 1;
        size_t off = ((size_t)b * NTOK + q0 + arow) * 32 + ahalf * 16;
        const uint4* sh = (const uint4*)(qsh + off);
        const uint4* sl = (const uint4*)(qsl + off);
        uint32_t* dh = sQh + arow * 36 + ahalf * 16;
        uint32_t* dl = sQl + arow * 36 + ahalf * 16;
#pragma unroll
        for (int j = 0; j < 4; j++) { *(uint4*)&dh[j * 4] = sh[j]; *(uint4*)&dl[j * 4] = sl[j]; }
    }

#define FL_ISSUE(c, s) do {                                                          \
        const char* _src = (const char*)(kvimg + ((size_t)b * nchunk + (c)) * FSTGW);\
        uint32_t _dst = stg_b + (uint32_t)(s) * (FSTGW * 4);                         \
        _Pragma("unroll")                                                            \
        for (int _t = 0; _t < 18; _t++) {                                            \
            int _idx = tid + _t * 128;                                               \
            CPA16(_dst + _idx * 16, _src + (size_t)_idx * 16);                       \
        }                                                                            \
    } while (0)

    float acc_o[8][4];
#pragma unroll
    for (int nn = 0; nn < 8; nn++)
#pragma unroll
        for (int q = 0; q < 4; q++) acc_o[nn][q] = 0.f;
    float mrun0 = -1e30f, mrun1 = -1e30f, l0 = 0.f, l1 = 0.f;

    FL_ISSUE(0, 0);
    CPA_COMMIT();

    for (int c = 0; c < nchunk; c++) {
        if (c + 1 < nchunk) FL_ISSUE(c + 1, (c + 1) & 1);
        CPA_COMMIT();
        CPA_WAIT1();
        __syncthreads();

        const uint32_t* stg = fsm + 4608 + (c & 1) * FSTGW;
        const uint32_t* sKh = stg;
        const uint32_t* sKl = stg + 2304;
        const uint32_t* sVh = stg + 4608;
        const uint32_t* sVl = stg + 6912;

        float s[8][4];
#pragma unroll
        for (int j = 0; j < 8; j++)
#pragma unroll
            for (int q = 0; q < 4; q++) s[j][q] = 0.f;

#pragma unroll
        for (int ks = 0; ks < 4; ks++) {
            uint32_t ah[4], al[4];
            int r = w * 16 + rA;
            int cc = 8 * ks + cA;
            ah[0] = sQh[r * 36 + cc];
            ah[1] = sQh[(r + 8) * 36 + cc];
            ah[2] = sQh[r * 36 + cc + 4];
            ah[3] = sQh[(r + 8) * 36 + cc + 4];
            al[0] = sQl[r * 36 + cc];
            al[1] = sQl[(r + 8) * 36 + cc];
            al[2] = sQl[r * 36 + cc + 4];
            al[3] = sQl[(r + 8) * 36 + cc + 4];
#pragma unroll
            for (int j = 0; j < 8; j++) {
                int n = j * 8 + rA;
                uint32_t bh0 = sKh[(8 * ks + cA) * 72 + n];
                uint32_t bh1 = sKh[(8 * ks + 4 + cA) * 72 + n];
                uint32_t bl0 = sKl[(8 * ks + cA) * 72 + n];
                uint32_t bl1 = sKl[(8 * ks + 4 + cA) * 72 + n];
                MMA16816(s[j], ah, bh0, bh1);
                MMA16816(s[j], ah, bl0, bl1);
                MMA16816(s[j], al, bh0, bh1);
            }
        }

        int cbase = c * 64;
        bool lastc = (cbase + 64 > m);
#pragma unroll
        for (int j = 0; j < 8; j++)
#pragma unroll
            for (int q = 0; q < 4; q++) {
                float v = s[j][q] * ATT_SCALE;
                if (lastc && (cbase + j * 8 + 2 * cA + (q & 1)) >= m) v = -1e30f;
                s[j][q] = v;
            }

        float mx0 = -1e30f, mx1 = -1e30f;
#pragma unroll
        for (int j = 0; j < 8; j++) {
            mx0 = fmaxf(mx0, fmaxf(s[j][0], s[j][1]));
            mx1 = fmaxf(mx1, fmaxf(s[j][2], s[j][3]));
        }
        mx0 = fmaxf(mx0, __shfl_xor_sync(0xffffffffu, mx0, 1));
        mx0 = fmaxf(mx0, __shfl_xor_sync(0xffffffffu, mx0, 2));
        mx1 = fmaxf(mx1, __shfl_xor_sync(0xffffffffu, mx1, 1));
        mx1 = fmaxf(mx1, __shfl_xor_sync(0xffffffffu, mx1, 2));
        float mn0 = fmaxf(mrun0, mx0), mn1 = fmaxf(mrun1, mx1);
        float sc0 = __expf(mrun0 - mn0), sc1 = __expf(mrun1 - mn1);
        mrun0 = mn0; mrun1 = mn1;

        float sum0 = 0.f, sum1 = 0.f;
#pragma unroll
        for (int j = 0; j < 8; j++) {
            s[j][0] = __expf(s[j][0] - mn0);
            s[j][1] = __expf(s[j][1] - mn0);
            s[j][2] = __expf(s[j][2] - mn1);
            s[j][3] = __expf(s[j][3] - mn1);
            sum0 += s[j][0] + s[j][1];
            sum1 += s[j][2] + s[j][3];
        }
        sum0 += __shfl_xor_sync(0xffffffffu, sum0, 1);
        sum0 += __shfl_xor_sync(0xffffffffu, sum0, 2);
        sum1 += __shfl_xor_sync(0xffffffffu, sum1, 1);
        sum1 += __shfl_xor_sync(0xffffffffu, sum1, 2);
        l0 = l0 * sc0 + sum0;
        l1 = l1 * sc1 + sum1;

#pragma unroll
        for (int nn = 0; nn < 8; nn++) {
            acc_o[nn][0] *= sc0; acc_o[nn][1] *= sc0;
            acc_o[nn][2] *= sc1; acc_o[nn][3] *= sc1;
        }

        uint32_t aph[4][4], apl[4][4];
#pragma unroll
        for (int kk = 0; kk < 4; kk++) {
            split2(s[2 * kk][0],     s[2 * kk][1],     aph[kk][0], apl[kk][0]);
            split2(s[2 * kk][2],     s[2 * kk][3],     aph[kk][1], apl[kk][1]);
            split2(s[2 * kk + 1][0], s[2 * kk + 1][1], aph[kk][2], apl[kk][2]);
            split2(s[2 * kk + 1][2], s[2 * kk + 1][3], aph[kk][3], apl[kk][3]);
        }

#pragma unroll
        for (int kk = 0; kk < 4; kk++) {
#pragma unroll
            for (int nn = 0; nn < 8; nn++) {
                int n = nn * 8 + rA;
                uint32_t vh0 = sVh[(8 * kk + cA) * 72 + n];
                uint32_t vh1 = sVh[(8 * kk + 4 + cA) * 72 + n];
                uint32_t vl0 = sVl[(8 * kk + cA) * 72 + n];
                uint32_t vl1 = sVl[(8 * kk + 4 + cA) * 72 + n];
                MMA16816(acc_o[nn], aph[kk], vh0, vh1);
                MMA16816(acc_o[nn], aph[kk], vl0, vl1);
                MMA16816(acc_o[nn], apl[kk], vh0, vh1);
            }
        }
        __syncthreads();
    }
#undef FL_ISSUE

    float inv0 = 1.f / l0, inv1 = 1.f / l1;
    size_t row0 = (size_t)b * NTOK + q0 + w * 16 + rA;
#pragma unroll
    for (int nn = 0; nn < 8; nn++) {
        int col = nn * 8 + 2 * cA;
        size_t w0 = row0 * 96 + (size_t)((hoff + col) >> 1);
        size_t w1 = (row0 + 8) * 96 + (size_t)((hoff + col) >> 1);
        uint32_t hi, lo;
        split2(acc_o[nn][0] * inv0, acc_o[nn][1] * inv0, hi, lo);
        xch[w0] = hi; xcl[w0] = lo;
        split2(acc_o[nn][2] * inv1, acc_o[nn][3] * inv1, hi, lo);
        xch[w1] = hi; xcl[w1] = lo;
    }
}

// ---------------- LayerNorm + exact GELU -> split bf16 -------------------------------
__device__ __forceinline__ float warpSum(float v) {
#pragma unroll
    for (int o = 16; o; o >>= 1) v += __shfl_xor_sync(0xffffffffu, v, o);
    return v;
}
__global__ void ln_gelu_kernel(const float* __restrict__ t, const float* __restrict__ g,
                               const float* __restrict__ bb,
                               __nv_bfloat16* __restrict__ th, __nv_bfloat16* __restrict__ tl) {
    size_t row = blockIdx.x;
    int tid = threadIdx.x;
    float v = t[row * NC + tid];
    __shared__ float sm[6];
    int lane = tid & 31, w = tid >> 5;
    float s = warpSum(v);
    if (lane == 0) sm[w] = s;
    __syncthreads();
    float mean = 0.f;
#pragma unroll
    for (int i = 0; i < 6; i++) mean += sm[i];
    mean *= (1.0f / 192.0f);
    float d = v - mean;
    __syncthreads();
    s = warpSum(d * d);
    if (lane == 0) sm[w] = s;
    __syncthreads();
    float var = 0.f;
#pragma unroll
    for (int i = 0; i < 6; i++) var += sm[i];
    var *= (1.0f / 192.0f);
    float y = d * rsqrtf(var + 1e-5f) * g[tid] + bb[tid];
    float r = y * normcdff(y);
    __nv_bfloat16 hi = __float2bfloat16(r);
    th[row * NC + tid] = hi;
    tl[row * NC + tid] = __float2bfloat16(r - __bfloat162float(hi));
}

// ---------------- depthwise 3x3 on v, residual add -----------------------------------
__global__ void dwconv_kernel(const float* __restrict__ kv, const float* __restrict__ lw,
                              const float* __restrict__ lb, float* __restrict__ vp,
                              int side, int m)
{
    long long idx = (long long)blockIdx.x * 256 + threadIdx.x;
    long long total = (long long)NB * m * 64;
    if (idx >= total) return;
    int hd = (int)(idx & 63);
    long long pm = idx >> 6;
    int p = (int)(pm % m);
    int b = (int)(pm / m);
    int y = p / side, x = p % side;
    const float* vbase = kv + (size_t)b * m * 128 + 64 + hd;
    float s = lb[hd];
#pragma unroll
    for (int dy = 0; dy < 3; dy++) {
        int yy = y + dy - 1;
        if (yy < 0 || yy >= side) continue;
#pragma unroll
        for (int dx = 0; dx < 3; dx++) {
            int xx = x + dx - 1;
            if (xx < 0 || xx >= side) continue;
            s += lw[hd * 9 + dy * 3 + dx] * vbase[(size_t)(yy * side + xx) * 128];
        }
    }
    vp[idx] = vbase[(size_t)p * 128] + s;
}

// ---------------- host orchestration ---------------------------------------------------
extern "C" void kernel_launch(void* const* d_in, const int* in_sizes, int n_in,
                              void* d_out, int out_size)
{
    (void)in_sizes; (void)n_in; (void)out_size;
    const float* x    = (const float*)d_in[0];
    const float* q_w  = (const float*)d_in[1];
    const float* q_b  = (const float*)d_in[2];
    const float* kv_w = (const float*)d_in[3];
    const float* kv_b = (const float*)d_in[4];
    const float* sr_w[3] = {(const float*)d_in[5], (const float*)d_in[7], (const float*)d_in[9]};
    const float* sr_b[3] = {(const float*)d_in[6], (const float*)d_in[8], (const float*)d_in[10]};
    const float* ln_g[3] = {(const float*)d_in[11], (const float*)d_in[13], (const float*)d_in[15]};
    const float* ln_b[3] = {(const float*)d_in[12], (const float*)d_in[14], (const float*)d_in[16]};
    const float* lc_w[3] = {(const float*)d_in[17], (const float*)d_in[19], (const float*)d_in[21]};
    const float* lc_b[3] = {(const float*)d_in[18], (const float*)d_in[20], (const float*)d_in[22]};
    const float* nn1_w = (const float*)d_in[23];
    const float* nn1_b = (const float*)d_in[24];
    float* out = (float*)d_out;

    float *p_t, *p_kv, *p_vp;
    __nv_bfloat16 *p_xh, *p_xl, *p_th, *p_tl;
    uint32_t *p_wp, *p_wq, *p_wkv, *p_wnn, *p_kvimg, *p_xch, *p_xcl, *p_qsh, *p_qsl;
    cudaGetSymbolAddress((void**)&p_t,    g_t);
    cudaGetSymbolAddress((void**)&p_kv,   g_kv);
    cudaGetSymbolAddress((void**)&p_vp,   g_vp);
    cudaGetSymbolAddress((void**)&p_xh,   g_xh);
    cudaGetSymbolAddress((void**)&p_xl,   g_xl);
    cudaGetSymbolAddress((void**)&p_th,   g_th);
    cudaGetSymbolAddress((void**)&p_tl,   g_tl);
    cudaGetSymbolAddress((void**)&p_wp,   g_wpack);
    cudaGetSymbolAddress((void**)&p_wq,   g_wq);
    cudaGetSymbolAddress((void**)&p_wkv,  g_wkv);
    cudaGetSymbolAddress((void**)&p_wnn,  g_wnn);
    cudaGetSymbolAddress((void**)&p_qsh,  g_qs_h);
    cudaGetSymbolAddress((void**)&p_qsl,  g_qs_l);
    cudaGetSymbolAddress((void**)&p_kvimg, g_kvimg);
    cudaGetSymbolAddress((void**)&p_xch,  g_xch);
    cudaGetSymbolAddress((void**)&p_xcl,  g_xcl);

    cudaFuncSetAttribute(conv_hmma_kernel, cudaFuncAttributeMaxDynamicSharedMemorySize,
                         2 * CSTGW * 4);
    cudaFuncSetAttribute(gemm_hmma_kernel, cudaFuncAttributeMaxDynamicSharedMemorySize,
                         2 * CSTGW * 4);
    cudaFuncSetAttribute(attn_flash_kernel, cudaFuncAttributeMaxDynamicSharedMemorySize,
                         (4608 + 2 * FSTGW) * 4);

    const int WPROJ = 12 * BIMG;

    prep_x_kernel<<<(NB * NTOK * NC + 255) / 256, 256>>>(x, p_xh, p_xl);
    prep_w_kernel<<<(WPROJ + 255) / 256, 256>>>(q_w, p_wq, 1);
    prep_w_kernel<<<(WPROJ + 255) / 256, 256>>>(kv_w, p_wkv, 1);
    prep_w_kernel<<<(WPROJ + 255) / 256, 256>>>(nn1_w, p_wnn, 1);

    // q projection -> split per-head q directly (prep_q fused into epilogue)
    gemm_hmma_kernel<<<dim3((NB * NTOK + 63) / 64, 2), 256, 2 * CSTGW * 4>>>(
        p_xh, p_xl, (const uint4*)p_wq, q_b, nullptr, p_qsh, p_qsl,
        (long long)NB * NTOK, NC, NC);

    const int KS[3] = {8, 4, 2};
    for (int h = 0; h < 3; h++) {
        int k = KS[h];
        int side = 64 - k + 1;
        int m = side * side;
        int k2 = k * k;
        int nchunk = (m + 63) / 64;
        long long Bm = (long long)NB * m;

        prep_w_kernel<<<(k2 * WPROJ + 255) / 256, 256>>>(sr_w[h], p_wp, k2);
        conv_hmma_kernel<<<dim3((int)((Bm + 63) / 64), 2), 256, 2 * CSTGW * 4>>>(
            p_xh, p_xl, (const uint4*)p_wp, sr_b[h], p_t, k, side, m);
        ln_gelu_kernel<<<NB * m, 192>>>(p_t, ln_g[h], ln_b[h], p_th, p_tl);

        gemm_hmma_kernel<<<dim3((int)((Bm + 63) / 64), 2), 256, 2 * CSTGW * 4>>>(
            p_th, p_tl, (const uint4*)p_wkv, kv_b, p_kv, nullptr, nullptr, Bm, 128, 128);

        dwconv_kernel<<<(int)(((long long)NB * m * 64 + 255) / 256), 256>>>(
            p_kv, lc_w[h], lc_b[h], p_vp, side, m);
        pack_kv_kernel<<<(NB * nchunk * FSTGW + 255) / 256, 256>>>(
            p_kv, p_vp, p_kvimg, m, nchunk);

        attn_flash_kernel<<<dim3(NTOK / 64, NB), 128, (4608 + 2 * FSTGW) * 4>>>(
            p_qsh + (size_t)h * NB * NTOK * 32, p_qsl + (size_t)h * NB * NTOK * 32,
            p_kvimg, p_xch, p_xcl, h * 64, m, nchunk);
    }

    gemm_hmma_kernel<<<dim3((NB * NTOK + 63) / 64, 2), 256, 2 * CSTGW * 4>>>(
        (const __nv_bfloat16*)p_xch, (const __nv_bfloat16*)p_xcl,
        (const uint4*)p_wnn, nn1_b, out, nullptr, nullptr,
        (long long)NB * NTOK, NC, NC);
}

// round 17
// speedup vs baseline: 1.2623x; 1.0134x over previous
#include <cuda_runtime.h>
#include <cuda_bf16.h>
#include <math.h>
#include <stdint.h>

#define NB   4
#define NTOK 4096
#define NC   192
#define MAXM 3969
#define BIMG 3456                        // B image words: 96 rows x 36 pitch
#define CSTGW 11520                      // stage words: Ah2304+Al2304+B0 3456+B1 3456
#define FSTGW 9216                       // flash stage words: kh/kl/vh/vl x 2304

static const float ATT_SCALE = 0.07216878364870323f; // 192^-0.5

// ---------------- scratch -------------------------------------------------------
__device__ float g_t[(size_t)NB * MAXM * NC];
__device__ float g_kv[NB * MAXM * 128];
__device__ __nv_bfloat16 g_xh[NB * NTOK * NC];
__device__ __nv_bfloat16 g_xl[NB * NTOK * NC];
__device__ __nv_bfloat16 g_th[(size_t)NB * MAXM * NC];
__device__ __nv_bfloat16 g_tl[(size_t)NB * MAXM * NC];
__device__ uint32_t g_xch[NB * NTOK * 96];
__device__ uint32_t g_xcl[NB * NTOK * 96];
__device__ uint32_t g_wpack[768 * BIMG];
__device__ uint32_t g_wq[12 * BIMG];
__device__ uint32_t g_wkv[12 * BIMG];
__device__ uint32_t g_wnn[12 * BIMG];
__device__ uint32_t g_qs_h[3 * NB * NTOK * 32];   // per-head split q (word pairs)
__device__ uint32_t g_qs_l[3 * NB * NTOK * 32];
__device__ uint32_t g_kvimg[NB * 63 * FSTGW];

// ---------------- helpers ---------------------------------------------------------
__device__ __forceinline__ uint32_t smem_u32(const void* p) {
    uint32_t a;
    asm("{ .reg .u64 t; cvta.to.shared.u64 t, %1; cvt.u32.u64 %0, t; }" : "=r"(a) : "l"(p));
    return a;
}
#define MMA16816(acc, a, b0, b1)                                                    \
    asm volatile("mma.sync.aligned.m16n8k16.row.col.f32.bf16.bf16.f32 "             \
        "{%0,%1,%2,%3}, {%4,%5,%6,%7}, {%8,%9}, {%0,%1,%2,%3};"                     \
        : "+f"((acc)[0]), "+f"((acc)[1]), "+f"((acc)[2]), "+f"((acc)[3])            \
        : "r"((a)[0]), "r"((a)[1]), "r"((a)[2]), "r"((a)[3]), "r"(b0), "r"(b1))
#define LDSM4(r0, r1, r2, r3, addr)                                                 \
    asm volatile("ldmatrix.sync.aligned.m8n8.x4.shared.b16 {%0,%1,%2,%3}, [%4];"    \
        : "=r"(r0), "=r"(r1), "=r"(r2), "=r"(r3) : "r"(addr))
#define LDSM2(r0, r1, addr)                                                         \
    asm volatile("ldmatrix.sync.aligned.m8n8.x2.shared.b16 {%0,%1}, [%2];"          \
        : "=r"(r0), "=r"(r1) : "r"(addr))
#define CPA16(dst, src)                                                             \
    asm volatile("cp.async.cg.shared.global [%0], [%1], 16;"                        \
        :: "r"(dst), "l"(src))
#define CPA_COMMIT() asm volatile("cp.async.commit_group;" ::: "memory")
#define CPA_WAIT1()  asm volatile("cp.async.wait_group 1;" ::: "memory")

__device__ __forceinline__ void split2(float a, float b, uint32_t& hi, uint32_t& lo) {
    __nv_bfloat16 ha = __float2bfloat16(a), hb = __float2bfloat16(b);
    float ra = a - __bfloat162float(ha);
    float rb = b - __bfloat162float(hb);
    __nv_bfloat16 la = __float2bfloat16(ra), lb = __float2bfloat16(rb);
    hi = ((uint32_t)*(unsigned short*)&hb << 16) | *(unsigned short*)&ha;
    lo = ((uint32_t)*(unsigned short*)&lb << 16) | *(unsigned short*)&la;
}

// ---------------- prep: split x into bf16 hi/lo -----------------------------------
__global__ void prep_x_kernel(const float* __restrict__ x, __nv_bfloat16* __restrict__ xh,
                              __nv_bfloat16* __restrict__ xl) {
    int i = blockIdx.x * 256 + threadIdx.x;
    if (i >= NB * NTOK * NC) return;
    float f = x[i];
    __nv_bfloat16 h = __float2bfloat16(f);
    xh[i] = h;
    xl[i] = __float2bfloat16(f - __bfloat162float(h));
}

// ---------------- prep: W -> n-major packed word images -----------------------------
__global__ void prep_w_kernel(const float* __restrict__ w, uint32_t* __restrict__ wp,
                              int k2) {
    int idx = blockIdx.x * 256 + threadIdx.x;
    int total = k2 * 12 * BIMG;
    if (idx >= total) return;
    int img = idx / BIMG, rem = idx % BIMG;
    int n = rem / 36, c2 = rem % 36;
    if (c2 >= 32) { wp[idx] = 0u; return; }
    int tap = img / 12, r = img % 12;
    int cb = r >> 2, r2 = r & 3;
    int cohalf = r2 >> 1, split = r2 & 1;
    int ci = cb * 64 + 2 * c2;
    int co = cohalf * 96 + n;
    float fe = w[((size_t)co * NC + ci) * k2 + tap];
    float fo = w[((size_t)co * NC + ci + 1) * k2 + tap];
    __nv_bfloat16 he = __float2bfloat16(fe), ho = __float2bfloat16(fo);
    __nv_bfloat16 ve = split ? __float2bfloat16(fe - __bfloat162float(he)) : he;
    __nv_bfloat16 vo = split ? __float2bfloat16(fo - __bfloat162float(ho)) : ho;
    uint32_t we = *(const unsigned short*)&ve;
    uint32_t wo = *(const unsigned short*)&vo;
    wp[idx] = (wo << 16) | we;
}

// ---------------- shared compute core (ldmatrix + MMA) ------------------------------
#define HMMA_GROUP_COMPUTE(soff)                                                     \
    _Pragma("unroll")                                                                \
    for (int ks = 0; ks < 4; ks++) {                                                 \
        uint32_t kb = (uint32_t)(ks * 32);                                           \
        uint32_t ah[4], ah2[4], al[4], al2[4];                                       \
        LDSM4(ah[0], ah[1], ah[2], ah[3], aoff0 + (soff) + kb);                      \
        LDSM4(ah2[0], ah2[1], ah2[2], ah2[3], aoff1 + (soff) + kb);                  \
        LDSM4(al[0], al[1], al[2], al[3], aoff0 + (soff) + 9216u + kb);              \
        LDSM4(al2[0], al2[1], al2[2], al2[3], aoff1 + (soff) + 9216u + kb);          \
        uint32_t wh[3][2], wl[3][2];                                                 \
        LDSM4(wh[0][0], wh[0][1], wh[1][0], wh[1][1], boff01 + (soff) + kb);         \
        LDSM2(wh[2][0], wh[2][1], boff2 + (soff) + kb);                              \
        LDSM4(wl[0][0], wl[0][1], wl[1][0], wl[1][1], boff01 + (soff) + 13824u + kb);\
        LDSM2(wl[2][0], wl[2][1], boff2 + (soff) + 13824u + kb);                     \
        _Pragma("unroll")                                                            \
        for (int j = 0; j < 3; j++) {                                                \
            MMA16816(acc[0][j], ah, wh[j][0], wh[j][1]);                             \
            MMA16816(acc[0][j], ah, wl[j][0], wl[j][1]);                             \
            MMA16816(acc[0][j], al, wh[j][0], wh[j][1]);                             \
            MMA16816(acc[1][j], ah2, wh[j][0], wh[j][1]);                            \
            MMA16816(acc[1][j], ah2, wl[j][0], wl[j][1]);                            \
            MMA16816(acc[1][j], al2, wh[j][0], wh[j][1]);                            \
        }                                                                            \
    }

// ---------------- conv: implicit GEMM, HMMA + ldmatrix, cp.async x2 ------------------
__global__ void __launch_bounds__(256, 2) conv_hmma_kernel(
    const __nv_bfloat16* __restrict__ xh, const __nv_bfloat16* __restrict__ xl,
    const uint4* __restrict__ wp, const float* __restrict__ bias,
    float* __restrict__ out, int k, int side, int m)
{
    extern __shared__ uint32_t dsm[];

    int tid = threadIdx.x;
    int lane = tid & 31, wid = tid >> 5;
    int wm = wid & 1, wn = wid >> 1;
    long long Bm = (long long)NB * m;

    int arow = tid >> 2, aq = tid & 3;
    long long apx = (long long)blockIdx.x * 64 + arow;
    long long apxc = apx < Bm - 1 ? apx : Bm - 1;
    int ab = (int)(apxc / m), app = (int)(apxc % m);
    int aoy = app / side, aox = app % side;
    size_t axbase = (size_t)ab * NTOK * NC;
    int half = blockIdx.y;
    int rA = lane >> 2, cA = lane & 3;

    uint32_t smbase = smem_u32(dsm);
    uint32_t awd = smbase + (uint32_t)(arow * 36 + aq * 8) * 4;
    uint32_t bwd = smbase + 4608u * 4;

    int lrow = lane & 15, lcol = lane >> 4;
    uint32_t aoff0 = smbase + (uint32_t)((wm * 32 + lrow) * 144 + lcol * 16);
    uint32_t aoff1 = aoff0 + 16 * 144;
    int brow = (lane & 7) + ((lane & 16) ? 8 : 0);
    int bcolb = ((lane >> 3) & 1) * 16;
    uint32_t boff01 = smbase + 4608u * 4 + (uint32_t)((wn * 24 + brow) * 144 + bcolb);
    uint32_t boff2  = smbase + 4608u * 4 + (uint32_t)((wn * 24 + 16 + (lane & 7)) * 144
                                                      + bcolb);

    float acc[2][3][4];
#pragma unroll
    for (int i = 0; i < 2; i++)
#pragma unroll
        for (int j = 0; j < 3; j++)
#pragma unroll
            for (int q = 0; q < 4; q++) acc[i][j][q] = 0.f;

    int k2 = k * k;
    int ng = k2 * 3;

#define CONV_ISSUE(g, s) do {                                                        \
        int _tap = (g) / 3, _cb = (g) - _tap * 3;                                    \
        int _dy = _tap / k, _dx = _tap - _dy * k;                                    \
        size_t _aoff = axbase + (size_t)((aoy + _dy) * 64 + aox + _dx) * NC          \
                     + _cb * 64 + aq * 16;                                           \
        uint32_t _soff = (uint32_t)(s) * (CSTGW * 4);                                \
        const char* _gh = (const char*)(xh + _aoff);                                 \
        const char* _gl = (const char*)(xl + _aoff);                                 \
        CPA16(awd + _soff,      _gh);                                                \
        CPA16(awd + _soff + 16, _gh + 16);                                           \
        CPA16(awd + _soff + 2304u * 4,      _gl);                                    \
        CPA16(awd + _soff + 2304u * 4 + 16, _gl + 16);                               \
        int _imgb = (_tap * 3 + _cb) * 4 + half * 2;                                 \
        const char* _gb = (const char*)(wp + (size_t)_imgb * (BIMG / 4));            \
        _Pragma("unroll")                                                            \
        for (int _i = 0; _i < 7; _i++) {                                             \
            int _idx = tid + _i * 256;                                               \
            if (_idx < 1728) CPA16(bwd + _soff + _idx * 16, _gb + (size_t)_idx * 16);\
        }                                                                            \
    } while (0)

    CONV_ISSUE(0, 0);
    CPA_COMMIT();

    for (int g = 0; g < ng; g++) {
        if (g + 1 < ng) CONV_ISSUE(g + 1, (g + 1) & 1);
        CPA_COMMIT();
        CPA_WAIT1();
        __syncthreads();

        uint32_t soff = (uint32_t)(g & 1) * (CSTGW * 4);
        HMMA_GROUP_COMPUTE(soff);
        __syncthreads();
    }
#undef CONV_ISSUE

#pragma unroll
    for (int i = 0; i < 2; i++) {
        long long row0 = (long long)blockIdx.x * 64 + wm * 32 + i * 16 + rA;
#pragma unroll
        for (int j = 0; j < 3; j++) {
            int col = half * 96 + wn * 24 + j * 8 + 2 * cA;
            float b0 = bias[col], b1 = bias[col + 1];
            if (row0 < Bm) {
                float2 v = make_float2(acc[i][j][0] + b0, acc[i][j][1] + b1);
                *(float2*)&out[row0 * NC + col] = v;
            }
            if (row0 + 8 < Bm) {
                float2 v = make_float2(acc[i][j][2] + b0, acc[i][j][3] + b1);
                *(float2*)&out[(row0 + 8) * NC + col] = v;
            }
        }
    }
}

// ---------------- projection GEMM on HMMA + ldmatrix ---------------------------------
__global__ void __launch_bounds__(256, 2) gemm_hmma_kernel(
    const __nv_bfloat16* __restrict__ Ah_g, const __nv_bfloat16* __restrict__ Al_g,
    const uint4* __restrict__ wimg, const float* __restrict__ bias,
    float* __restrict__ out, uint32_t* __restrict__ qs_h, uint32_t* __restrict__ qs_l,
    long long rows, int ldout, int Nout)
{
    extern __shared__ uint32_t dsm[];

    int tid = threadIdx.x;
    int lane = tid & 31, wid = tid >> 5;
    int wm = wid & 1, wn = wid >> 1;

    int arow = tid >> 2, aq = tid & 3;
    long long r = (long long)blockIdx.x * 64 + arow;
    long long rc = r < rows - 1 ? r : rows - 1;
    int half = blockIdx.y;
    int rA = lane >> 2, cA = lane & 3;

    uint32_t smbase = smem_u32(dsm);
    uint32_t awd = smbase + (uint32_t)(arow * 36 + aq * 8) * 4;
    uint32_t bwd = smbase + 4608u * 4;

    int lrow = lane & 15, lcol = lane >> 4;
    uint32_t aoff0 = smbase + (uint32_t)((wm * 32 + lrow) * 144 + lcol * 16);
    uint32_t aoff1 = aoff0 + 16 * 144;
    int brow = (lane & 7) + ((lane & 16) ? 8 : 0);
    int bcolb = ((lane >> 3) & 1) * 16;
    uint32_t boff01 = smbase + 4608u * 4 + (uint32_t)((wn * 24 + brow) * 144 + bcolb);
    uint32_t boff2  = smbase + 4608u * 4 + (uint32_t)((wn * 24 + 16 + (lane & 7)) * 144
                                                      + bcolb);

    float acc[2][3][4];
#pragma unroll
    for (int i = 0; i < 2; i++)
#pragma unroll
        for (int j = 0; j < 3; j++)
#pragma unroll
            for (int q = 0; q < 4; q++) acc[i][j][q] = 0.f;

#define PROJ_ISSUE(g, s) do {                                                        \
        size_t _aoff = (size_t)rc * NC + (g) * 64 + aq * 16;                         \
        uint32_t _soff = (uint32_t)(s) * (CSTGW * 4);                                \
        const char* _gh = (const char*)(Ah_g + _aoff);                               \
        const char* _gl = (const char*)(Al_g + _aoff);                               \
        CPA16(awd + _soff,      _gh);                                                \
        CPA16(awd + _soff + 16, _gh + 16);                                           \
        CPA16(awd + _soff + 2304u * 4,      _gl);                                    \
        CPA16(awd + _soff + 2304u * 4 + 16, _gl + 16);                               \
        int _imgb = (g) * 4 + half * 2;                                              \
        const char* _gb = (const char*)(wimg + (size_t)_imgb * (BIMG / 4));          \
        _Pragma("unroll")                                                            \
        for (int _i = 0; _i < 7; _i++) {                                             \
            int _idx = tid + _i * 256;                                               \
            if (_idx < 1728) CPA16(bwd + _soff + _idx * 16, _gb + (size_t)_idx * 16);\
        }                                                                            \
    } while (0)

    PROJ_ISSUE(0, 0);
    CPA_COMMIT();

    for (int g = 0; g < 3; g++) {
        if (g + 1 < 3) PROJ_ISSUE(g + 1, (g + 1) & 1);
        CPA_COMMIT();
        CPA_WAIT1();
        __syncthreads();

        uint32_t soff = (uint32_t)(g & 1) * (CSTGW * 4);
        HMMA_GROUP_COMPUTE(soff);
        __syncthreads();
    }
#undef PROJ_ISSUE

#pragma unroll
    for (int i = 0; i < 2; i++) {
        long long row0 = (long long)blockIdx.x * 64 + wm * 32 + i * 16 + rA;
#pragma unroll
        for (int j = 0; j < 3; j++) {
            int col = half * 96 + wn * 24 + j * 8 + 2 * cA;
            if (col >= Nout) continue;
            float b0 = bias[col], b1 = bias[col + 1];
            if (qs_h) {
                size_t wbase = ((size_t)(col / 64) * rows) * 32 + (size_t)((col % 64) >> 1);
                uint32_t hi, lo;
                if (row0 < rows) {
                    split2(acc[i][j][0] + b0, acc[i][j][1] + b1, hi, lo);
                    qs_h[wbase + (size_t)row0 * 32] = hi;
                    qs_l[wbase + (size_t)row0 * 32] = lo;
                }
                if (row0 + 8 < rows) {
                    split2(acc[i][j][2] + b0, acc[i][j][3] + b1, hi, lo);
                    qs_h[wbase + (size_t)(row0 + 8) * 32] = hi;
                    qs_l[wbase + (size_t)(row0 + 8) * 32] = lo;
                }
            } else {
                if (row0 < rows) {
                    float2 v = make_float2(acc[i][j][0] + b0, acc[i][j][1] + b1);
                    *(float2*)&out[row0 * ldout + col] = v;
                }
                if (row0 + 8 < rows) {
                    float2 v = make_float2(acc[i][j][2] + b0, acc[i][j][3] + b1);
                    *(float2*)&out[(row0 + 8) * ldout + col] = v;
                }
            }
        }
    }
}

// ---------------- fused dwconv + pack: kv -> per-chunk [kh|kl|vh|vl] images ----------
// One thread per hi/lo WORD-PAIR. pairsec 0 = k (straight copy+split),
// pairsec 1 = v (dwconv computed once per element, same summation order as before).
__global__ void pack_kv_kernel(const float* __restrict__ kv,
                               const float* __restrict__ lw, const float* __restrict__ lb,
                               uint32_t* __restrict__ img, int m, int nchunk, int side) {
    int idx = blockIdx.x * 256 + threadIdx.x;
    int total = NB * nchunk * 2 * 2304;
    if (idx >= total) return;
    int b = idx / (nchunk * 2 * 2304);
    int rem = idx % (nchunk * 2 * 2304);
    int c = rem / (2 * 2304);
    int r2 = rem % (2 * 2304);
    int pairsec = r2 / 2304;
    int r3 = r2 % 2304;
    int c2 = r3 / 72, n = r3 % 72;
    size_t base = ((size_t)b * nchunk + c) * FSTGW + (size_t)pairsec * 4608 + c2 * 72 + n;
    if (n >= 64) { img[base] = 0u; img[base + 2304] = 0u; return; }
    float f0, f1;
    if (pairsec == 0) {
        int mi = c * 64 + n;
        if (mi < m) {
            const float* kr = kv + ((size_t)b * m + mi) * 128;
            f0 = kr[2 * c2];
            f1 = kr[2 * c2 + 1];
        } else { f0 = f1 = 0.f; }
    } else {
        const float* vb = kv + (size_t)b * m * 128 + 64 + n;
        float fv[2];
#pragma unroll
        for (int e = 0; e < 2; e++) {
            int p = c * 64 + 2 * c2 + e;
            float r = 0.f;
            if (p < m) {
                int y = p / side, x0 = p % side;
                float s = lb[n];
#pragma unroll
                for (int dy = 0; dy < 3; dy++) {
                    int yy = y + dy - 1;
                    if (yy < 0 || yy >= side) continue;
#pragma unroll
                    for (int dx = 0; dx < 3; dx++) {
                        int xx = x0 + dx - 1;
                        if (xx < 0 || xx >= side) continue;
                        s += lw[n * 9 + dy * 3 + dx] * vb[(size_t)(yy * side + xx) * 128];
                    }
                }
                r = vb[(size_t)p * 128] + s;
            }
            fv[e] = r;
        }
        f0 = fv[0]; f1 = fv[1];
    }
    uint32_t hi, lo;
    split2(f0, f1, hi, lo);
    img[base] = hi;
    img[base + 2304] = lo;
}

// ---------------- fused flash attention: 64 q-rows per CTA (128 thr, 2 CTA/SM) -------
__global__ void __launch_bounds__(128, 2) attn_flash_kernel(
    const uint32_t* __restrict__ qsh, const uint32_t* __restrict__ qsl,
    const uint32_t* __restrict__ kvimg,
    uint32_t* __restrict__ xch, uint32_t* __restrict__ xcl,
    int hoff, int m, int nchunk)
{
    extern __shared__ uint32_t fsm[];
    uint32_t* sQh = fsm;              // 64*36
    uint32_t* sQl = fsm + 2304;       // 64*36

    int tid = threadIdx.x, lane = tid & 31, w = tid >> 5;
    int rA = lane >> 2, cA = lane & 3;
    int b = blockIdx.y;
    int q0 = blockIdx.x * 64;

    uint32_t stg_b = smem_u32(fsm) + 4608u * 4;

    {
        int arow = tid >> 1, ahalf = tid & 1;
        size_t off = ((size_t)b * NTOK + q0 + arow) * 32 + ahalf * 16;
        const uint4* sh = (const uint4*)(qsh + off);
        const uint4* sl = (const uint4*)(qsl + off);
        uint32_t* dh = sQh + arow * 36 + ahalf * 16;
        uint32_t* dl = sQl + arow * 36 + ahalf * 16;
#pragma unroll
        for (int j = 0; j < 4; j++) { *(uint4*)&dh[j * 4] = sh[j]; *(uint4*)&dl[j * 4] = sl[j]; }
    }

#define FL_ISSUE(c, s) do {                                                          \
        const char* _src = (const char*)(kvimg + ((size_t)b * nchunk + (c)) * FSTGW);\
        uint32_t _dst = stg_b + (uint32_t)(s) * (FSTGW * 4);                         \
        _Pragma("unroll")                                                            \
        for (int _t = 0; _t < 18; _t++) {                                            \
            int _idx = tid + _t * 128;                                               \
            CPA16(_dst + _idx * 16, _src + (size_t)_idx * 16);                       \
        }                                                                            \
    } while (0)

    float acc_o[8][4];
#pragma unroll
    for (int nn = 0; nn < 8; nn++)
#pragma unroll
        for (int q = 0; q < 4; q++) acc_o[nn][q] = 0.f;
    float mrun0 = -1e30f, mrun1 = -1e30f, l0 = 0.f, l1 = 0.f;

    FL_ISSUE(0, 0);
    CPA_COMMIT();

    for (int c = 0; c < nchunk; c++) {
        if (c + 1 < nchunk) FL_ISSUE(c + 1, (c + 1) & 1);
        CPA_COMMIT();
        CPA_WAIT1();
        __syncthreads();

        const uint32_t* stg = fsm + 4608 + (c & 1) * FSTGW;
        const uint32_t* sKh = stg;
        const uint32_t* sKl = stg + 2304;
        const uint32_t* sVh = stg + 4608;
        const uint32_t* sVl = stg + 6912;

        float s[8][4];
#pragma unroll
        for (int j = 0; j < 8; j++)
#pragma unroll
            for (int q = 0; q < 4; q++) s[j][q] = 0.f;

#pragma unroll
        for (int ks = 0; ks < 4; ks++) {
            uint32_t ah[4], al[4];
            int r = w * 16 + rA;
            int cc = 8 * ks + cA;
            ah[0] = sQh[r * 36 + cc];
            ah[1] = sQh[(r + 8) * 36 + cc];
            ah[2] = sQh[r * 36 + cc + 4];
            ah[3] = sQh[(r + 8) * 36 + cc + 4];
            al[0] = sQl[r * 36 + cc];
            al[1] = sQl[(r + 8) * 36 + cc];
            al[2] = sQl[r * 36 + cc + 4];
            al[3] = sQl[(r + 8) * 36 + cc + 4];
#pragma unroll
            for (int j = 0; j < 8; j++) {
                int n = j * 8 + rA;
                uint32_t bh0 = sKh[(8 * ks + cA) * 72 + n];
                uint32_t bh1 = sKh[(8 * ks + 4 + cA) * 72 + n];
                uint32_t bl0 = sKl[(8 * ks + cA) * 72 + n];
                uint32_t bl1 = sKl[(8 * ks + 4 + cA) * 72 + n];
                MMA16816(s[j], ah, bh0, bh1);
                MMA16816(s[j], ah, bl0, bl1);
                MMA16816(s[j], al, bh0, bh1);
            }
        }

        int cbase = c * 64;
        bool lastc = (cbase + 64 > m);
#pragma unroll
        for (int j = 0; j < 8; j++)
#pragma unroll
            for (int q = 0; q < 4; q++) {
                float v = s[j][q] * ATT_SCALE;
                if (lastc && (cbase + j * 8 + 2 * cA + (q & 1)) >= m) v = -1e30f;
                s[j][q] = v;
            }

        float mx0 = -1e30f, mx1 = -1e30f;
#pragma unroll
        for (int j = 0; j < 8; j++) {
            mx0 = fmaxf(mx0, fmaxf(s[j][0], s[j][1]));
            mx1 = fmaxf(mx1, fmaxf(s[j][2], s[j][3]));
        }
        mx0 = fmaxf(mx0, __shfl_xor_sync(0xffffffffu, mx0, 1));
        mx0 = fmaxf(mx0, __shfl_xor_sync(0xffffffffu, mx0, 2));
        mx1 = fmaxf(mx1, __shfl_xor_sync(0xffffffffu, mx1, 1));
        mx1 = fmaxf(mx1, __shfl_xor_sync(0xffffffffu, mx1, 2));
        float mn0 = fmaxf(mrun0, mx0), mn1 = fmaxf(mrun1, mx1);
        float sc0 = __expf(mrun0 - mn0), sc1 = __expf(mrun1 - mn1);
        mrun0 = mn0; mrun1 = mn1;

        float sum0 = 0.f, sum1 = 0.f;
#pragma unroll
        for (int j = 0; j < 8; j++) {
            s[j][0] = __expf(s[j][0] - mn0);
            s[j][1] = __expf(s[j][1] - mn0);
            s[j][2] = __expf(s[j][2] - mn1);
            s[j][3] = __expf(s[j][3] - mn1);
            sum0 += s[j][0] + s[j][1];
            sum1 += s[j][2] + s[j][3];
        }
        sum0 += __shfl_xor_sync(0xffffffffu, sum0, 1);
        sum0 += __shfl_xor_sync(0xffffffffu, sum0, 2);
        sum1 += __shfl_xor_sync(0xffffffffu, sum1, 1);
        sum1 += __shfl_xor_sync(0xffffffffu, sum1, 2);
        l0 = l0 * sc0 + sum0;
        l1 = l1 * sc1 + sum1;

#pragma unroll
        for (int nn = 0; nn < 8; nn++) {
            acc_o[nn][0] *= sc0; acc_o[nn][1] *= sc0;
            acc_o[nn][2] *= sc1; acc_o[nn][3] *= sc1;
        }

        uint32_t aph[4][4], apl[4][4];
#pragma unroll
        for (int kk = 0; kk < 4; kk++) {
            split2(s[2 * kk][0],     s[2 * kk][1],     aph[kk][0], apl[kk][0]);
            split2(s[2 * kk][2],     s[2 * kk][3],     aph[kk][1], apl[kk][1]);
            split2(s[2 * kk + 1][0], s[2 * kk + 1][1], aph[kk][2], apl[kk][2]);
            split2(s[2 * kk + 1][2], s[2 * kk + 1][3], aph[kk][3], apl[kk][3]);
        }

#pragma unroll
        for (int kk = 0; kk < 4; kk++) {
#pragma unroll
            for (int nn = 0; nn < 8; nn++) {
                int n = nn * 8 + rA;
                uint32_t vh0 = sVh[(8 * kk + cA) * 72 + n];
                uint32_t vh1 = sVh[(8 * kk + 4 + cA) * 72 + n];
                uint32_t vl0 = sVl[(8 * kk + cA) * 72 + n];
                uint32_t vl1 = sVl[(8 * kk + 4 + cA) * 72 + n];
                MMA16816(acc_o[nn], aph[kk], vh0, vh1);
                MMA16816(acc_o[nn], aph[kk], vl0, vl1);
                MMA16816(acc_o[nn], apl[kk], vh0, vh1);
            }
        }
        __syncthreads();
    }
#undef FL_ISSUE

    float inv0 = 1.f / l0, inv1 = 1.f / l1;
    size_t row0 = (size_t)b * NTOK + q0 + w * 16 + rA;
#pragma unroll
    for (int nn = 0; nn < 8; nn++) {
        int col = nn * 8 + 2 * cA;
        size_t w0 = row0 * 96 + (size_t)((hoff + col) >> 1);
        size_t w1 = (row0 + 8) * 96 + (size_t)((hoff + col) >> 1);
        uint32_t hi, lo;
        split2(acc_o[nn][0] * inv0, acc_o[nn][1] * inv0, hi, lo);
        xch[w0] = hi; xcl[w0] = lo;
        split2(acc_o[nn][2] * inv1, acc_o[nn][3] * inv1, hi, lo);
        xch[w1] = hi; xcl[w1] = lo;
    }
}

// ---------------- LayerNorm + exact GELU -> split bf16 -------------------------------
__device__ __forceinline__ float warpSum(float v) {
#pragma unroll
    for (int o = 16; o; o >>= 1) v += __shfl_xor_sync(0xffffffffu, v, o);
    return v;
}
__global__ void ln_gelu_kernel(const float* __restrict__ t, const float* __restrict__ g,
                               const float* __restrict__ bb,
                               __nv_bfloat16* __restrict__ th, __nv_bfloat16* __restrict__ tl) {
    size_t row = blockIdx.x;
    int tid = threadIdx.x;
    float v = t[row * NC + tid];
    __shared__ float sm[6];
    int lane = tid & 31, w = tid >> 5;
    float s = warpSum(v);
    if (lane == 0) sm[w] = s;
    __syncthreads();
    float mean = 0.f;
#pragma unroll
    for (int i = 0; i < 6; i++) mean += sm[i];
    mean *= (1.0f / 192.0f);
    float d = v - mean;
    __syncthreads();
    s = warpSum(d * d);
    if (lane == 0) sm[w] = s;
    __syncthreads();
    float var = 0.f;
#pragma unroll
    for (int i = 0; i < 6; i++) var += sm[i];
    var *= (1.0f / 192.0f);
    float y = d * rsqrtf(var + 1e-5f) * g[tid] + bb[tid];
    float r = y * normcdff(y);
    __nv_bfloat16 hi = __float2bfloat16(r);
    th[row * NC + tid] = hi;
    tl[row * NC + tid] = __float2bfloat16(r - __bfloat162float(hi));
}

// ---------------- host orchestration ---------------------------------------------------
extern "C" void kernel_launch(void* const* d_in, const int* in_sizes, int n_in,
                              void* d_out, int out_size)
{
    (void)in_sizes; (void)n_in; (void)out_size;
    const float* x    = (const float*)d_in[0];
    const float* q_w  = (const float*)d_in[1];
    const float* q_b  = (const float*)d_in[2];
    const float* kv_w = (const float*)d_in[3];
    const float* kv_b = (const float*)d_in[4];
    const float* sr_w[3] = {(const float*)d_in[5], (const float*)d_in[7], (const float*)d_in[9]};
    const float* sr_b[3] = {(const float*)d_in[6], (const float*)d_in[8], (const float*)d_in[10]};
    const float* ln_g[3] = {(const float*)d_in[11], (const float*)d_in[13], (const float*)d_in[15]};
    const float* ln_b[3] = {(const float*)d_in[12], (const float*)d_in[14], (const float*)d_in[16]};
    const float* lc_w[3] = {(const float*)d_in[17], (const float*)d_in[19], (const float*)d_in[21]};
    const float* lc_b[3] = {(const float*)d_in[18], (const float*)d_in[20], (const float*)d_in[22]};
    const float* nn1_w = (const float*)d_in[23];
    const float* nn1_b = (const float*)d_in[24];
    float* out = (float*)d_out;

    float *p_t, *p_kv;
    __nv_bfloat16 *p_xh, *p_xl, *p_th, *p_tl;
    uint32_t *p_wp, *p_wq, *p_wkv, *p_wnn, *p_kvimg, *p_xch, *p_xcl, *p_qsh, *p_qsl;
    cudaGetSymbolAddress((void**)&p_t,    g_t);
    cudaGetSymbolAddress((void**)&p_kv,   g_kv);
    cudaGetSymbolAddress((void**)&p_xh,   g_xh);
    cudaGetSymbolAddress((void**)&p_xl,   g_xl);
    cudaGetSymbolAddress((void**)&p_th,   g_th);
    cudaGetSymbolAddress((void**)&p_tl,   g_tl);
    cudaGetSymbolAddress((void**)&p_wp,   g_wpack);
    cudaGetSymbolAddress((void**)&p_wq,   g_wq);
    cudaGetSymbolAddress((void**)&p_wkv,  g_wkv);
    cudaGetSymbolAddress((void**)&p_wnn,  g_wnn);
    cudaGetSymbolAddress((void**)&p_qsh,  g_qs_h);
    cudaGetSymbolAddress((void**)&p_qsl,  g_qs_l);
    cudaGetSymbolAddress((void**)&p_kvimg, g_kvimg);
    cudaGetSymbolAddress((void**)&p_xch,  g_xch);
    cudaGetSymbolAddress((void**)&p_xcl,  g_xcl);

    cudaFuncSetAttribute(conv_hmma_kernel, cudaFuncAttributeMaxDynamicSharedMemorySize,
                         2 * CSTGW * 4);
    cudaFuncSetAttribute(gemm_hmma_kernel, cudaFuncAttributeMaxDynamicSharedMemorySize,
                         2 * CSTGW * 4);
    cudaFuncSetAttribute(attn_flash_kernel, cudaFuncAttributeMaxDynamicSharedMemorySize,
                         (4608 + 2 * FSTGW) * 4);

    const int WPROJ = 12 * BIMG;

    prep_x_kernel<<<(NB * NTOK * NC + 255) / 256, 256>>>(x, p_xh, p_xl);
    prep_w_kernel<<<(WPROJ + 255) / 256, 256>>>(q_w, p_wq, 1);
    prep_w_kernel<<<(WPROJ + 255) / 256, 256>>>(kv_w, p_wkv, 1);
    prep_w_kernel<<<(WPROJ + 255) / 256, 256>>>(nn1_w, p_wnn, 1);

    // q projection -> split per-head q directly
    gemm_hmma_kernel<<<dim3((NB * NTOK + 63) / 64, 2), 256, 2 * CSTGW * 4>>>(
        p_xh, p_xl, (const uint4*)p_wq, q_b, nullptr, p_qsh, p_qsl,
        (long long)NB * NTOK, NC, NC);

    const int KS[3] = {8, 4, 2};
    for (int h = 0; h < 3; h++) {
        int k = KS[h];
        int side = 64 - k + 1;
        int m = side * side;
        int k2 = k * k;
        int nchunk = (m + 63) / 64;
        long long Bm = (long long)NB * m;

        prep_w_kernel<<<(k2 * WPROJ + 255) / 256, 256>>>(sr_w[h], p_wp, k2);
        conv_hmma_kernel<<<dim3((int)((Bm + 63) / 64), 2), 256, 2 * CSTGW * 4>>>(
            p_xh, p_xl, (const uint4*)p_wp, sr_b[h], p_t, k, side, m);
        ln_gelu_kernel<<<NB * m, 192>>>(p_t, ln_g[h], ln_b[h], p_th, p_tl);

        gemm_hmma_kernel<<<dim3((int)((Bm + 63) / 64), 2), 256, 2 * CSTGW * 4>>>(
            p_th, p_tl, (const uint4*)p_wkv, kv_b, p_kv, nullptr, nullptr, Bm, 128, 128);

        pack_kv_kernel<<<(NB * nchunk * 2 * 2304 + 255) / 256, 256>>>(
            p_kv, lc_w[h], lc_b[h], p_kvimg, m, nchunk, side);

        attn_flash_kernel<<<dim3(NTOK / 64, NB), 128, (4608 + 2 * FSTGW) * 4>>>(
            p_qsh + (size_t)h * NB * NTOK * 32, p_qsl + (size_t)h * NB * NTOK * 32,
            p_kvimg, p_xch, p_xcl, h * 64, m, nchunk);
    }

    gemm_hmma_kernel<<<dim3((NB * NTOK + 63) / 64, 2), 256, 2 * CSTGW * 4>>>(
        (const __nv_bfloat16*)p_xch, (const __nv_bfloat16*)p_xcl,
        (const uint4*)p_wnn, nn1_b, out, nullptr, nullptr,
        (long long)NB * NTOK, NC, NC);
}